// round 13
// baseline (speedup 1.0000x reference)
#include <cuda_runtime.h>
#include <cstdint>
#include <math.h>

#define NT 1024
#define CD 768
#define NH 16
#define DH 48
#define HD 1536
#define CPD 128

typedef unsigned long long ull;

// ---------------- f32x2 packed-math helpers (sm_100+) -----------------------
__device__ __forceinline__ ull pk2(float lo, float hi) {
    ull r; asm("mov.b64 %0, {%1, %2};" : "=l"(r) : "f"(lo), "f"(hi)); return r;
}
__device__ __forceinline__ void fma2(ull &d, ull a, ull b) {
    asm("fma.rn.f32x2 %0, %1, %2, %0;" : "+l"(d) : "l"(a), "l"(b));
}
__device__ __forceinline__ ull add2(ull a, ull b) {
    ull r; asm("add.rn.f32x2 %0, %1, %2;" : "=l"(r) : "l"(a), "l"(b)); return r;
}
__device__ __forceinline__ ull mul2(ull a, ull b) {
    ull r; asm("mul.rn.f32x2 %0, %1, %2;" : "=l"(r) : "l"(a), "l"(b)); return r;
}
__device__ __forceinline__ float2 up2(ull v) {
    float2 r; asm("mov.b64 {%0, %1}, %2;" : "=f"(r.x), "=f"(r.y) : "l"(v)); return r;
}
__device__ __forceinline__ float sigm(float x) { return 1.f/(1.f+__expf(-x)); }
__device__ __forceinline__ uint32_t smem_u32(const void* p) {
    uint32_t a;
    asm("{ .reg .u64 t; cvta.to.shared.u64 t, %1; cvt.u32.u64 %0, t; }" : "=r"(a) : "l"(p));
    return a;
}
__device__ __forceinline__ void cp_async16(uint32_t dst, const void* src) {
    asm volatile("cp.async.ca.shared.global [%0], [%1], 16;" :: "r"(dst), "l"(src));
}

// ---------------- scratch (device globals; no allocations allowed) ----------
__device__ __align__(16) float g_lna[NT*CD];
__device__ __align__(16) float g_sn1[NT*CD];
__device__ __align__(16) float g_sn2[NT*CD];
__device__ __align__(16) float g_an[NT*CD];
__device__ __align__(16) float g_an2[NT*CD];
__device__ __align__(16) float g_o[NT*CD];
__device__ __align__(16) float g_attout[2*NT*CD];    // split-K partials
__device__ __align__(16) float g_bout[NT*CD];
__device__ __align__(16) float g_h1[NT*HD];
__device__ __align__(16) float g_t3[2*NT*CD];        // split-K partials
__device__ __align__(16) float g_tgk[NT*2*CD];       // attn adaLN tg|tk, stride 1536
__device__ __align__(16) float g_tgk2[NT*2*CD];      // transition adaLN tg|tk
__device__ __align__(16) float g_qkvg[NT*4*CD];      // q|k|v|gate, stride 3072
__device__ __align__(16) float g_ts2[NT*2*CD];       // s@wso | s@ws2, stride 1536
__device__ __align__(16) float g_h12[NT*2*HD];       // h1|h2, stride 3072
__device__ __align__(16) float g_bqkv[4*CD];
__device__ __align__(16) float g_wgp[CPD*NH];
__device__ __align__(16) ull   g_wpk[8*CPD];         // packed h-pairs
__device__ __align__(16) float g_cc[2*NH];
__device__ __align__(16) float g_bias[(size_t)NH*NT*NT];   // 64 MB [h][q][k]

// ---------------- LayerNorm of a and s; sn1 = LN(s)*sg1, sn2 = LN(s)*sg2 ----
__global__ void ln_kernel(const float* __restrict__ a, const float* __restrict__ s,
                          const float* __restrict__ sg1, const float* __restrict__ sg2)
{
    int r = blockIdx.x, t = threadIdx.x;
    const float* ar = a + (size_t)r*CD;
    const float* sr = s + (size_t)r*CD;
    float va[3], vs[3];
    float s0=0.f,s1=0.f,s2=0.f,s3=0.f;
#pragma unroll
    for (int i=0;i<3;i++){
        va[i]=ar[t+256*i]; vs[i]=sr[t+256*i];
        s0+=va[i]; s1+=va[i]*va[i]; s2+=vs[i]; s3+=vs[i]*vs[i];
    }
    __shared__ float red[4][8];
    int lane=t&31, w=t>>5;
#pragma unroll
    for (int o=16;o;o>>=1){
        s0+=__shfl_xor_sync(0xffffffffu,s0,o);
        s1+=__shfl_xor_sync(0xffffffffu,s1,o);
        s2+=__shfl_xor_sync(0xffffffffu,s2,o);
        s3+=__shfl_xor_sync(0xffffffffu,s3,o);
    }
    if (lane==0){ red[0][w]=s0; red[1][w]=s1; red[2][w]=s2; red[3][w]=s3; }
    __syncthreads();
    float S0=0.f,S1=0.f,S2=0.f,S3=0.f;
#pragma unroll
    for (int i=0;i<8;i++){ S0+=red[0][i]; S1+=red[1][i]; S2+=red[2][i]; S3+=red[3][i]; }
    float mua=S0*(1.f/768.f), rsa=rsqrtf(S1*(1.f/768.f)-mua*mua+1e-5f);
    float mus=S2*(1.f/768.f), rss=rsqrtf(S3*(1.f/768.f)-mus*mus+1e-5f);
#pragma unroll
    for (int i=0;i<3;i++){
        int c=t+256*i; size_t idx=(size_t)r*CD+c;
        g_lna[idx]=(va[i]-mua)*rsa;
        float sv=(vs[i]-mus)*rss;
        g_sn1[idx]=sv*sg1[c];
        g_sn2[idx]=sv*sg2[c];
    }
}

__global__ void bfill_kernel(const float* __restrict__ bq)
{
    int i = blockIdx.x*256 + threadIdx.x;
    g_bqkv[i] = (i < CD) ? bq[i] : 0.f;
}

// ---------------- SGEMM: 64x64 tile, 64 threads, 8x8/thread, f32x2 (R9) -----
__global__ void __launch_bounds__(64) sgemm64_kernel(
    const float* __restrict__ A, int lda,
    const float* __restrict__ B0, const float* __restrict__ B1,
    const float* __restrict__ B2, const float* __restrict__ B3,
    int bN, const float* __restrict__ biasv,
    float* __restrict__ C, int Nn, int K, int cz)
{
    __shared__ __align__(16) float As[2][8][64];
    __shared__ __align__(16) float Bs[2][8][64];
    int t = threadIdx.x;
    int z = blockIdx.z;
    int tx = t & 7, ty = t >> 3;
    int row0 = blockIdx.y << 6;
    int cb = blockIdx.x;
    int perSrc = bN >> 6;
    int si = cb / perSrc;
    const float* Bsel = (si==0) ? B0 : (si==1) ? B1 : (si==2) ? B2 : B3;
    int colSrc = (cb - si*perSrc) << 6;

    const float* Ag = A + (size_t)(row0 + t)*lda + (size_t)z*K;
    const float* Bg = Bsel + (size_t)z*K*bN + (size_t)(t>>3)*bN + colSrc + ((t&7)<<2);
    C += (size_t)z*cz;

    ull acc[8][4];
#pragma unroll
    for (int i=0;i<8;i++)
#pragma unroll
        for (int j=0;j<4;j++) acc[i][j]=0ull;

    int nt = K >> 3;
    float4 a0 = *(const float4*)(Ag);
    float4 a1 = *(const float4*)(Ag + 4);
    float4 b0 = *(const float4*)(Bg);
    float4 b1 = *(const float4*)(Bg + 32);
    {
        As[0][0][t]=a0.x; As[0][1][t]=a0.y; As[0][2][t]=a0.z; As[0][3][t]=a0.w;
        As[0][4][t]=a1.x; As[0][5][t]=a1.y; As[0][6][t]=a1.z; As[0][7][t]=a1.w;
        *(float4*)&Bs[0][t>>3][(t&7)<<2] = b0;
        *(float4*)&Bs[0][t>>3][((t&7)<<2)+32] = b1;
    }
    __syncthreads();

    for (int kt = 0; kt < nt; kt++) {
        int cur = kt & 1;
        bool more = (kt+1) < nt;
        if (more) {
            a0 = *(const float4*)(Ag + (kt+1)*8);
            a1 = *(const float4*)(Ag + (kt+1)*8 + 4);
            b0 = *(const float4*)(Bg + (size_t)(kt+1)*8*bN);
            b1 = *(const float4*)(Bg + (size_t)(kt+1)*8*bN + 32);
        }
#pragma unroll
        for (int kk = 0; kk < 8; kk++) {
            float4 av0 = *(const float4*)&As[cur][kk][ty<<3];
            float4 av1 = *(const float4*)&As[cur][kk][(ty<<3)+4];
            float4 bv0 = *(const float4*)&Bs[cur][kk][tx<<3];
            float4 bv1 = *(const float4*)&Bs[cur][kk][(tx<<3)+4];
            ull bp0 = pk2(bv0.x,bv0.y), bp1 = pk2(bv0.z,bv0.w);
            ull bp2 = pk2(bv1.x,bv1.y), bp3 = pk2(bv1.z,bv1.w);
            float aarr[8] = {av0.x,av0.y,av0.z,av0.w,av1.x,av1.y,av1.z,av1.w};
#pragma unroll
            for (int i=0;i<8;i++){
                ull aa = pk2(aarr[i], aarr[i]);
                fma2(acc[i][0], aa, bp0);
                fma2(acc[i][1], aa, bp1);
                fma2(acc[i][2], aa, bp2);
                fma2(acc[i][3], aa, bp3);
            }
        }
        if (more) {
            int nx = cur ^ 1;
            As[nx][0][t]=a0.x; As[nx][1][t]=a0.y; As[nx][2][t]=a0.z; As[nx][3][t]=a0.w;
            As[nx][4][t]=a1.x; As[nx][5][t]=a1.y; As[nx][6][t]=a1.z; As[nx][7][t]=a1.w;
            *(float4*)&Bs[nx][t>>3][(t&7)<<2] = b0;
            *(float4*)&Bs[nx][t>>3][((t&7)<<2)+32] = b1;
            __syncthreads();
        }
    }

    int col = (cb<<6) + (tx<<3);
    float4 bb0 = make_float4(0.f,0.f,0.f,0.f), bb1 = bb0;
    if (biasv) { bb0 = *(const float4*)(biasv + col); bb1 = *(const float4*)(biasv + col + 4); }
#pragma unroll
    for (int i=0;i<8;i++){
        int r = row0 + (ty<<3) + i;
        float2 p0=up2(acc[i][0]), p1=up2(acc[i][1]), p2=up2(acc[i][2]), p3=up2(acc[i][3]);
        float4 o0 = make_float4(p0.x+bb0.x, p0.y+bb0.y, p1.x+bb0.z, p1.y+bb0.w);
        float4 o1 = make_float4(p2.x+bb1.x, p2.y+bb1.y, p3.x+bb1.z, p3.y+bb1.w);
        *(float4*)(C + (size_t)r*Nn + col) = o0;
        *(float4*)(C + (size_t)r*Nn + col + 4) = o1;
    }
}

// ---------------- adaLN combine: an = sigmoid(tg+bg)*lna + tk ---------------
__global__ void adaln_combine_kernel(const float* __restrict__ tgk,
                                     const float* __restrict__ bgv,
                                     float* __restrict__ outp)
{
    int i = blockIdx.x*256 + threadIdx.x;
    int r = i / CD, c = i - r*CD;
    float tg = tgk[(size_t)r*1536 + c];
    float tk = tgk[(size_t)r*1536 + 768 + c];
    outp[i] = sigm(tg + bgv[c])*g_lna[i] + tk;
}

// ---------------- pair-bias precompute: wgp, packed h-pairs, c1/c2 ----------
__global__ void pair_prep_kernel(const float* __restrict__ gp,
                                 const float* __restrict__ bp,
                                 const float* __restrict__ wp)
{
    int j = threadIdx.x;  // 128
    float wg[NH];
#pragma unroll
    for (int h=0; h<NH; h++){ wg[h] = gp[j]*wp[j*NH+h]; g_wgp[j*NH+h] = wg[h]; }
#pragma unroll
    for (int m=0; m<8; m++) g_wpk[m*CPD + j] = pk2(wg[2*m], wg[2*m+1]);
    __syncthreads();
    if (j < NH) {
        float c1=0.f, c2=0.f;
        for (int jj=0; jj<CPD; jj++){ c1 += bp[jj]*wp[jj*NH+j]; c2 += g_wgp[jj*NH+j]; }
        g_cc[j]=c1; g_cc[NH+j]=c2;
    }
}

// ---------------- pair bias v4: cp.async double-buffered pipeline -----------
// Thread owns 4 pairs; k in 8 chunks of 16 cols; chunk c+1 loads via LDGSTS
// into the alternate buffer while chunk c computes. Row stride 20 floats
// (80B, 16B-aligned for cp.async).
#define PB_XBUF (512*20)                       // floats per buffer
#define PB_SMEM (2*PB_XBUF*4 + 128*8*8)        // 81920 + 8192 = 90112
__global__ void __launch_bounds__(128) pair_bias_kernel(
    const float* __restrict__ pair, const float* __restrict__ beta)
{
    extern __shared__ __align__(16) float smem[];
    float* xs0 = smem;                          // [512][20]
    float* xs1 = smem + PB_XBUF;                // [512][20]
    ull* wks = (ull*)(smem + 2*PB_XBUF);        // [128 k][8 m]
    __shared__ float csm[2*NH];

    int t = threadIdx.x;
    int q = blockIdx.x >> 1;
    int k0 = (blockIdx.x & 1) << 9;

    // stage weights transposed: wks[k][m] = g_wpk[m*128 + k]
    for (int i = t; i < 1024; i += 128) {
        int k = i >> 3, m = i & 7;
        wks[(k<<3) + m] = g_wpk[m*CPD + k];
    }
    if (t < 2*NH) csm[t] = g_cc[t];

    const float* base = pair + (((size_t)q<<10) + k0)*CPD;
    uint32_t xs_sa[2] = { smem_u32(xs0), smem_u32(xs1) };

    // issue chunk 0
    {
#pragma unroll
        for (int it=0; it<16; it++) {
            int g = (it<<7) + t;                // 0..2047 float4 slots
            int row = g >> 2, j = g & 3;        // 4 float4 per row
            cp_async16(xs_sa[0] + (row*20 + (j<<2))*4,
                       base + (size_t)row*CPD + (j<<2));
        }
        asm volatile("cp.async.commit_group;");
    }

    ull acc[4][8];
#pragma unroll
    for (int i=0;i<4;i++)
#pragma unroll
        for (int m=0;m<8;m++) acc[i][m]=0ull;
    float sm[4] = {0.f,0.f,0.f,0.f};
    float sq[4] = {0.f,0.f,0.f,0.f};

    for (int c = 0; c < 8; c++) {
        if (c+1 < 8) {
            const float* src = base + ((c+1)<<4);
            uint32_t dst = xs_sa[(c+1)&1];
#pragma unroll
            for (int it=0; it<16; it++) {
                int g = (it<<7) + t;
                int row = g >> 2, j = g & 3;
                cp_async16(dst + (row*20 + (j<<2))*4,
                           src + (size_t)row*CPD + (j<<2));
            }
            asm volatile("cp.async.commit_group;");
            asm volatile("cp.async.wait_group 1;");
        } else {
            asm volatile("cp.async.wait_group 0;");
        }
        __syncthreads();
        const float* xb = (c & 1) ? xs1 : xs0;
#pragma unroll
        for (int kk=0; kk<16; kk++) {
            const ull* wr = wks + ((c<<4)+kk)*8;
            ull w0=wr[0], w1=wr[1], w2=wr[2], w3=wr[3];
            ull w4=wr[4], w5=wr[5], w6=wr[6], w7=wr[7];
#pragma unroll
            for (int i=0;i<4;i++){
                float xv = xb[(t + (i<<7))*20 + kk];
                sm[i] += xv;
                sq[i] = fmaf(xv, xv, sq[i]);
                ull xx = pk2(xv, xv);
                fma2(acc[i][0], xx, w0); fma2(acc[i][1], xx, w1);
                fma2(acc[i][2], xx, w2); fma2(acc[i][3], xx, w3);
                fma2(acc[i][4], xx, w4); fma2(acc[i][5], xx, w5);
                fma2(acc[i][6], xx, w6); fma2(acc[i][7], xx, w7);
            }
        }
        __syncthreads();   // all threads done with xb before it is re-filled
    }

#pragma unroll
    for (int i=0;i<4;i++){
        int p = t + (i<<7);
        int kk = k0 + p;
        float mu = sm[i]*(1.f/128.f);
        float rs = rsqrtf(sq[i]*(1.f/128.f) - mu*mu + 1e-5f);
        float murs = mu*rs;
        float bv = beta[((size_t)q<<10) + kk];
#pragma unroll
        for (int m=0;m<8;m++){
            float2 v = up2(acc[i][m]);
            int h0 = m<<1;
            float z0 = rs*v.x - murs*csm[NH+h0]   + csm[h0]   + bv;
            float z1 = rs*v.y - murs*csm[NH+h0+1] + csm[h0+1] + bv;
            g_bias[((size_t)h0<<20)     + ((size_t)q<<10) + kk] = z0;
            g_bias[((size_t)(h0+1)<<20) + ((size_t)q<<10) + kk] = z1;
        }
    }
}

// ---------------- flash attention (f32x2) + fused output gate (R9) ----------
__global__ void __launch_bounds__(128) attn_kernel(
    const float* __restrict__ qp, const float* __restrict__ kp,
    const float* __restrict__ vp, const float* __restrict__ gatep)
{
    __shared__ __align__(16) float pool[6144];
    __shared__ float Ms[64], Ls[64];
    int t = threadIdx.x;
    int half = t>>6, ql = t&63;
    int h = blockIdx.y;
    int qr = (blockIdx.x<<6) + ql;
    const float scale = 0.14433756729740643f;
    ull q2[24];
#pragma unroll
    for (int d4=0; d4<12; d4++){
        float4 qq = *(const float4*)(qp + (size_t)qr*3072 + h*48 + (d4<<2));
        q2[d4*2]   = pk2(qq.x*scale, qq.y*scale);
        q2[d4*2+1] = pk2(qq.z*scale, qq.w*scale);
    }
    float m = -1e30f, l = 0.f;
    ull acc2[24];
#pragma unroll
    for (int i=0;i<24;i++) acc2[i]=0ull;
    int kb = half<<9;
    const float* brow = g_bias + ((size_t)h<<20) + ((size_t)qr<<10) + kb;
    for (int kt=0; kt<512; kt+=32) {
        __syncthreads();
#pragma unroll
        for (int it=0; it<6; it++) {
            int i4 = t + (it<<7);
            int d4 = i4 % 12;
            int rem = i4 / 12;
            int j = rem & 31, hh = rem >> 5;
            int krow = (hh<<9) + kt + j;
            ((float4*)pool)[i4]      = *(const float4*)(kp + (size_t)krow*3072 + h*48 + (d4<<2));
            ((float4*)pool)[768+i4]  = *(const float4*)(vp + (size_t)krow*3072 + h*48 + (d4<<2));
        }
        __syncthreads();
        float bb[32];
#pragma unroll
        for (int i=0;i<8;i++){
            float4 b4 = *(const float4*)(brow + kt + (i<<2));
            bb[i*4]=b4.x; bb[i*4+1]=b4.y; bb[i*4+2]=b4.z; bb[i*4+3]=b4.w;
        }
        const float* Kt = pool + half*1536;
        const float* Vt = pool + 3072 + half*1536;
        for (int j=0; j<32; j++) {
            const ull* kr2 = (const ull*)(Kt + j*48);
            ull d2 = 0ull;
#pragma unroll
            for (int i=0;i<24;i++) fma2(d2, q2[i], kr2[i]);
            float2 dd = up2(d2);
            float sc = dd.x + dd.y + bb[j];
            if (sc > m) {
                float corr = __expf(m - sc);
                l *= corr;
                ull cp = pk2(corr, corr);
#pragma unroll
                for (int i=0;i<24;i++) acc2[i] = mul2(acc2[i], cp);
                m = sc;
            }
            float pw = __expf(sc - m);
            l += pw;
            ull pp = pk2(pw, pw);
            const ull* vr2 = (const ull*)(Vt + j*48);
#pragma unroll
            for (int i=0;i<24;i++) fma2(acc2[i], pp, vr2[i]);
        }
    }
    __syncthreads();
    if (half == 1) {
        Ms[ql]=m; Ls[ql]=l;
#pragma unroll
        for (int i=0;i<24;i++){
            float2 v = up2(acc2[i]);
            pool[ql*48+2*i]=v.x; pool[ql*48+2*i+1]=v.y;
        }
    }
    __syncthreads();
    if (half == 0) {
        float m2=Ms[ql], l2=Ls[ql];
        float mn=fmaxf(m,m2);
        float c1=__expf(m-mn), c2=__expf(m2-mn);
        float inv=1.f/(l*c1 + l2*c2);
#pragma unroll
        for (int i=0;i<24;i++){
            float2 v = up2(acc2[i]);
            float g0 = sigm(gatep[(size_t)qr*3072 + h*48 + 2*i]);
            float g1 = sigm(gatep[(size_t)qr*3072 + h*48 + 2*i+1]);
            g_o[(size_t)qr*CD + h*48 + 2*i]   = (v.x*c1 + pool[ql*48+2*i]*c2)*inv*g0;
            g_o[(size_t)qr*CD + h*48 + 2*i+1] = (v.y*c1 + pool[ql*48+2*i+1]*c2)*inv*g1;
        }
    }
}

// ---------------- small elementwise kernels ---------------------------------
__global__ void bout_kernel(const float* __restrict__ bso) {
    int i = blockIdx.x*256 + threadIdx.x;
    int r = i / CD, c = i - r*CD;
    float att = g_attout[i] + g_attout[NT*CD + i];
    g_bout[i] = sigm(g_ts2[(size_t)r*1536 + c] + bso[c])*att;
}
__global__ void swiglu_kernel() {
    int i = blockIdx.x*256 + threadIdx.x;
    int r = i / HD, c = i - r*HD;
    float x = g_h12[(size_t)r*3072 + c];
    float y = g_h12[(size_t)r*3072 + 1536 + c];
    g_h1[i] = x*sigm(x)*y;
}
__global__ void final_kernel(const float* __restrict__ bs2, float* __restrict__ outp) {
    int i = blockIdx.x*256 + threadIdx.x;
    int r = i / CD, c = i - r*CD;
    float t3 = g_t3[i] + g_t3[NT*CD + i];
    outp[i] = g_bout[i] + sigm(g_ts2[(size_t)r*1536 + 768 + c] + bs2[c])*t3;
}

// ---------------- launch: dual-stream overlap --------------------------------
extern "C" void kernel_launch(void* const* d_in, const int* in_sizes, int n_in,
                              void* d_out, int out_size)
{
    (void)in_sizes; (void)n_in; (void)out_size;
    const float* a     = (const float*)d_in[0];
    const float* s     = (const float*)d_in[1];
    const float* pair  = (const float*)d_in[2];
    const float* beta  = (const float*)d_in[3];
    const float* sg1   = (const float*)d_in[4];
    const float* wg1   = (const float*)d_in[5];
    const float* bg1   = (const float*)d_in[6];
    const float* wsk1  = (const float*)d_in[7];
    const float* wq    = (const float*)d_in[8];
    const float* bq    = (const float*)d_in[9];
    const float* wk    = (const float*)d_in[10];
    const float* wv    = (const float*)d_in[11];
    const float* gp    = (const float*)d_in[12];
    const float* bp    = (const float*)d_in[13];
    const float* wp    = (const float*)d_in[14];
    const float* wgate = (const float*)d_in[15];
    const float* wo    = (const float*)d_in[16];
    const float* wso   = (const float*)d_in[17];
    const float* bso   = (const float*)d_in[18];
    const float* sg2   = (const float*)d_in[19];
    const float* wg2   = (const float*)d_in[20];
    const float* bg2   = (const float*)d_in[21];
    const float* wsk2  = (const float*)d_in[22];
    const float* w1    = (const float*)d_in[23];
    const float* w2    = (const float*)d_in[24];
    const float* w3    = (const float*)d_in[25];
    const float* ws2   = (const float*)d_in[26];
    const float* bs2   = (const float*)d_in[27];

    float *p_sn1,*p_sn2,*p_an,*p_an2,*p_o,*p_attout,*p_h1,*p_t3,*p_tgk,*p_tgk2,
          *p_qkvg,*p_ts2,*p_h12,*p_bqkv;
    cudaGetSymbolAddress((void**)&p_sn1,   g_sn1);
    cudaGetSymbolAddress((void**)&p_sn2,   g_sn2);
    cudaGetSymbolAddress((void**)&p_an,    g_an);
    cudaGetSymbolAddress((void**)&p_an2,   g_an2);
    cudaGetSymbolAddress((void**)&p_o,     g_o);
    cudaGetSymbolAddress((void**)&p_attout,g_attout);
    cudaGetSymbolAddress((void**)&p_h1,    g_h1);
    cudaGetSymbolAddress((void**)&p_t3,    g_t3);
    cudaGetSymbolAddress((void**)&p_tgk,   g_tgk);
    cudaGetSymbolAddress((void**)&p_tgk2,  g_tgk2);
    cudaGetSymbolAddress((void**)&p_qkvg,  g_qkvg);
    cudaGetSymbolAddress((void**)&p_ts2,   g_ts2);
    cudaGetSymbolAddress((void**)&p_h12,   g_h12);
    cudaGetSymbolAddress((void**)&p_bqkv,  g_bqkv);

    static cudaStream_t s1 = nullptr;
    static cudaEvent_t eFork, eLn, ePair, eTs2, eT3;
    if (!s1) {
        cudaFuncSetAttribute(pair_bias_kernel,
                             cudaFuncAttributeMaxDynamicSharedMemorySize, PB_SMEM);
        cudaStreamCreateWithFlags(&s1, cudaStreamNonBlocking);
        cudaEventCreateWithFlags(&eFork, cudaEventDisableTiming);
        cudaEventCreateWithFlags(&eLn,   cudaEventDisableTiming);
        cudaEventCreateWithFlags(&ePair, cudaEventDisableTiming);
        cudaEventCreateWithFlags(&eTs2,  cudaEventDisableTiming);
        cudaEventCreateWithFlags(&eT3,   cudaEventDisableTiming);
    }

    // ---- fork immediately: s1 starts pair work while legacy does LN ----
    cudaEventRecord(eFork, 0);
    cudaStreamWaitEvent(s1, eFork, 0);

    // s1: pair chain
    pair_prep_kernel<<<1, 128, 0, s1>>>(gp, bp, wp);
    pair_bias_kernel<<<2048, 128, PB_SMEM, s1>>>(pair, beta);
    cudaEventRecord(ePair, s1);
    sgemm64_kernel<<<dim3(24,16,1), 64, 0, s1>>>(s, CD, wso, ws2, wso, wso, CD,
                                                 nullptr, p_ts2, 1536, CD, 0);
    cudaEventRecord(eTs2, s1);

    // legacy: LN prep
    ln_kernel<<<NT, 256>>>(a, s, sg1, sg2);
    bfill_kernel<<<12, 256>>>(bq);
    cudaEventRecord(eLn, 0);

    // s1: transition chain (needs ln -> g_sn2)
    cudaStreamWaitEvent(s1, eLn, 0);
    sgemm64_kernel<<<dim3(24,16,1), 64, 0, s1>>>(p_sn2, CD, wg2, wsk2, wg2, wg2, CD,
                                                 nullptr, p_tgk2, 1536, CD, 0);
    adaln_combine_kernel<<<NT*CD/256, 256, 0, s1>>>(p_tgk2, bg2, p_an2);
    sgemm64_kernel<<<dim3(48,16,1), 64, 0, s1>>>(p_an2, CD, w1, w2, w1, w1, HD,
                                                 nullptr, p_h12, 3072, CD, 0);
    swiglu_kernel<<<NT*HD/256, 256, 0, s1>>>();
    sgemm64_kernel<<<dim3(12,16,2), 64, 0, s1>>>(p_h1, HD, w3, w3, w3, w3, CD,
                                                 nullptr, p_t3, CD, CD, NT*CD);
    cudaEventRecord(eT3, s1);

    // legacy: attention chain
    sgemm64_kernel<<<dim3(24,16,1), 64>>>(p_sn1, CD, wg1, wsk1, wg1, wg1, CD,
                                          nullptr, p_tgk, 1536, CD, 0);
    adaln_combine_kernel<<<NT*CD/256, 256>>>(p_tgk, bg1, p_an);
    sgemm64_kernel<<<dim3(48,16,1), 64>>>(p_an, CD, wq, wk, wv, wgate, CD,
                                          p_bqkv, p_qkvg, 3072, CD, 0);
    cudaStreamWaitEvent(0, ePair, 0);
    attn_kernel<<<dim3(16, 16), 128>>>(p_qkvg, p_qkvg + 768, p_qkvg + 1536, p_qkvg + 2304);
    sgemm64_kernel<<<dim3(12,16,2), 64>>>(p_o, CD, wo, wo, wo, wo, CD,
                                          nullptr, p_attout, CD, 384, NT*CD);
    cudaStreamWaitEvent(0, eTs2, 0);
    bout_kernel<<<NT*CD/256, 256>>>(bso);
    cudaStreamWaitEvent(0, eT3, 0);       // join s1 back before final
    final_kernel<<<NT*CD/256, 256>>>(bs2, (float*)d_out);
}

// round 14
// speedup vs baseline: 1.0265x; 1.0265x over previous
#include <cuda_runtime.h>
#include <cstdint>
#include <math.h>

#define NT 1024
#define CD 768
#define NH 16
#define DH 48
#define HD 1536
#define CPD 128

typedef unsigned long long ull;

// ---------------- f32x2 packed-math helpers (sm_100+) -----------------------
__device__ __forceinline__ ull pk2(float lo, float hi) {
    ull r; asm("mov.b64 %0, {%1, %2};" : "=l"(r) : "f"(lo), "f"(hi)); return r;
}
__device__ __forceinline__ void fma2(ull &d, ull a, ull b) {
    asm("fma.rn.f32x2 %0, %1, %2, %0;" : "+l"(d) : "l"(a), "l"(b));
}
__device__ __forceinline__ ull add2(ull a, ull b) {
    ull r; asm("add.rn.f32x2 %0, %1, %2;" : "=l"(r) : "l"(a), "l"(b)); return r;
}
__device__ __forceinline__ ull mul2(ull a, ull b) {
    ull r; asm("mul.rn.f32x2 %0, %1, %2;" : "=l"(r) : "l"(a), "l"(b)); return r;
}
__device__ __forceinline__ float2 up2(ull v) {
    float2 r; asm("mov.b64 {%0, %1}, %2;" : "=f"(r.x), "=f"(r.y) : "l"(v)); return r;
}
__device__ __forceinline__ float sigm(float x) { return 1.f/(1.f+__expf(-x)); }

// ---------------- scratch (device globals; no allocations allowed) ----------
__device__ __align__(16) float g_lna[NT*CD];
__device__ __align__(16) float g_sn1[NT*CD];
__device__ __align__(16) float g_sn2[NT*CD];
__device__ __align__(16) float g_an[NT*CD];
__device__ __align__(16) float g_an2[NT*CD];
__device__ __align__(16) float g_o[NT*CD];
__device__ __align__(16) float g_attout[2*NT*CD];    // split-K partials
__device__ __align__(16) float g_bout[NT*CD];
__device__ __align__(16) float g_h1[NT*HD];
__device__ __align__(16) float g_t3[2*NT*CD];        // split-K partials
__device__ __align__(16) float g_tgk[NT*2*CD];       // attn adaLN tg|tk, stride 1536
__device__ __align__(16) float g_tgk2[NT*2*CD];      // transition adaLN tg|tk
__device__ __align__(16) float g_qkvg[NT*4*CD];      // q|k|v|gate, stride 3072
__device__ __align__(16) float g_ts2[NT*2*CD];       // s@wso | s@ws2, stride 1536
__device__ __align__(16) float g_h12[NT*2*HD];       // h1|h2, stride 3072
__device__ __align__(16) float g_bqkv[4*CD];
__device__ __align__(16) float g_wgp[CPD*NH];
__device__ __align__(16) ull   g_wpk[8*CPD];         // packed h-pairs
__device__ __align__(16) float g_cc[2*NH];
__device__ __align__(16) float g_bias[(size_t)NH*NT*NT];   // 64 MB [h][q][k]

// ---------------- LayerNorm of a and s; sn1 = LN(s)*sg1, sn2 = LN(s)*sg2 ----
__global__ void ln_kernel(const float* __restrict__ a, const float* __restrict__ s,
                          const float* __restrict__ sg1, const float* __restrict__ sg2)
{
    int r = blockIdx.x, t = threadIdx.x;
    const float* ar = a + (size_t)r*CD;
    const float* sr = s + (size_t)r*CD;
    float va[3], vs[3];
    float s0=0.f,s1=0.f,s2=0.f,s3=0.f;
#pragma unroll
    for (int i=0;i<3;i++){
        va[i]=ar[t+256*i]; vs[i]=sr[t+256*i];
        s0+=va[i]; s1+=va[i]*va[i]; s2+=vs[i]; s3+=vs[i]*vs[i];
    }
    __shared__ float red[4][8];
    int lane=t&31, w=t>>5;
#pragma unroll
    for (int o=16;o;o>>=1){
        s0+=__shfl_xor_sync(0xffffffffu,s0,o);
        s1+=__shfl_xor_sync(0xffffffffu,s1,o);
        s2+=__shfl_xor_sync(0xffffffffu,s2,o);
        s3+=__shfl_xor_sync(0xffffffffu,s3,o);
    }
    if (lane==0){ red[0][w]=s0; red[1][w]=s1; red[2][w]=s2; red[3][w]=s3; }
    __syncthreads();
    float S0=0.f,S1=0.f,S2=0.f,S3=0.f;
#pragma unroll
    for (int i=0;i<8;i++){ S0+=red[0][i]; S1+=red[1][i]; S2+=red[2][i]; S3+=red[3][i]; }
    float mua=S0*(1.f/768.f), rsa=rsqrtf(S1*(1.f/768.f)-mua*mua+1e-5f);
    float mus=S2*(1.f/768.f), rss=rsqrtf(S3*(1.f/768.f)-mus*mus+1e-5f);
#pragma unroll
    for (int i=0;i<3;i++){
        int c=t+256*i; size_t idx=(size_t)r*CD+c;
        g_lna[idx]=(va[i]-mua)*rsa;
        float sv=(vs[i]-mus)*rss;
        g_sn1[idx]=sv*sg1[c];
        g_sn2[idx]=sv*sg2[c];
    }
}

__global__ void bfill_kernel(const float* __restrict__ bq)
{
    int i = blockIdx.x*256 + threadIdx.x;
    g_bqkv[i] = (i < CD) ? bq[i] : 0.f;
}

// ---------------- SGEMM: 64x64 tile, 64 threads, 8x8/thread, f32x2 (R9) -----
__global__ void __launch_bounds__(64) sgemm64_kernel(
    const float* __restrict__ A, int lda,
    const float* __restrict__ B0, const float* __restrict__ B1,
    const float* __restrict__ B2, const float* __restrict__ B3,
    int bN, const float* __restrict__ biasv,
    float* __restrict__ C, int Nn, int K, int cz)
{
    __shared__ __align__(16) float As[2][8][64];
    __shared__ __align__(16) float Bs[2][8][64];
    int t = threadIdx.x;
    int z = blockIdx.z;
    int tx = t & 7, ty = t >> 3;
    int row0 = blockIdx.y << 6;
    int cb = blockIdx.x;
    int perSrc = bN >> 6;
    int si = cb / perSrc;
    const float* Bsel = (si==0) ? B0 : (si==1) ? B1 : (si==2) ? B2 : B3;
    int colSrc = (cb - si*perSrc) << 6;

    const float* Ag = A + (size_t)(row0 + t)*lda + (size_t)z*K;
    const float* Bg = Bsel + (size_t)z*K*bN + (size_t)(t>>3)*bN + colSrc + ((t&7)<<2);
    C += (size_t)z*cz;

    ull acc[8][4];
#pragma unroll
    for (int i=0;i<8;i++)
#pragma unroll
        for (int j=0;j<4;j++) acc[i][j]=0ull;

    int nt = K >> 3;
    float4 a0 = *(const float4*)(Ag);
    float4 a1 = *(const float4*)(Ag + 4);
    float4 b0 = *(const float4*)(Bg);
    float4 b1 = *(const float4*)(Bg + 32);
    {
        As[0][0][t]=a0.x; As[0][1][t]=a0.y; As[0][2][t]=a0.z; As[0][3][t]=a0.w;
        As[0][4][t]=a1.x; As[0][5][t]=a1.y; As[0][6][t]=a1.z; As[0][7][t]=a1.w;
        *(float4*)&Bs[0][t>>3][(t&7)<<2] = b0;
        *(float4*)&Bs[0][t>>3][((t&7)<<2)+32] = b1;
    }
    __syncthreads();

    for (int kt = 0; kt < nt; kt++) {
        int cur = kt & 1;
        bool more = (kt+1) < nt;
        if (more) {
            a0 = *(const float4*)(Ag + (kt+1)*8);
            a1 = *(const float4*)(Ag + (kt+1)*8 + 4);
            b0 = *(const float4*)(Bg + (size_t)(kt+1)*8*bN);
            b1 = *(const float4*)(Bg + (size_t)(kt+1)*8*bN + 32);
        }
#pragma unroll
        for (int kk = 0; kk < 8; kk++) {
            float4 av0 = *(const float4*)&As[cur][kk][ty<<3];
            float4 av1 = *(const float4*)&As[cur][kk][(ty<<3)+4];
            float4 bv0 = *(const float4*)&Bs[cur][kk][tx<<3];
            float4 bv1 = *(const float4*)&Bs[cur][kk][(tx<<3)+4];
            ull bp0 = pk2(bv0.x,bv0.y), bp1 = pk2(bv0.z,bv0.w);
            ull bp2 = pk2(bv1.x,bv1.y), bp3 = pk2(bv1.z,bv1.w);
            float aarr[8] = {av0.x,av0.y,av0.z,av0.w,av1.x,av1.y,av1.z,av1.w};
#pragma unroll
            for (int i=0;i<8;i++){
                ull aa = pk2(aarr[i], aarr[i]);
                fma2(acc[i][0], aa, bp0);
                fma2(acc[i][1], aa, bp1);
                fma2(acc[i][2], aa, bp2);
                fma2(acc[i][3], aa, bp3);
            }
        }
        if (more) {
            int nx = cur ^ 1;
            As[nx][0][t]=a0.x; As[nx][1][t]=a0.y; As[nx][2][t]=a0.z; As[nx][3][t]=a0.w;
            As[nx][4][t]=a1.x; As[nx][5][t]=a1.y; As[nx][6][t]=a1.z; As[nx][7][t]=a1.w;
            *(float4*)&Bs[nx][t>>3][(t&7)<<2] = b0;
            *(float4*)&Bs[nx][t>>3][((t&7)<<2)+32] = b1;
            __syncthreads();
        }
    }

    int col = (cb<<6) + (tx<<3);
    float4 bb0 = make_float4(0.f,0.f,0.f,0.f), bb1 = bb0;
    if (biasv) { bb0 = *(const float4*)(biasv + col); bb1 = *(const float4*)(biasv + col + 4); }
#pragma unroll
    for (int i=0;i<8;i++){
        int r = row0 + (ty<<3) + i;
        float2 p0=up2(acc[i][0]), p1=up2(acc[i][1]), p2=up2(acc[i][2]), p3=up2(acc[i][3]);
        float4 o0 = make_float4(p0.x+bb0.x, p0.y+bb0.y, p1.x+bb0.z, p1.y+bb0.w);
        float4 o1 = make_float4(p2.x+bb1.x, p2.y+bb1.y, p3.x+bb1.z, p3.y+bb1.w);
        *(float4*)(C + (size_t)r*Nn + col) = o0;
        *(float4*)(C + (size_t)r*Nn + col + 4) = o1;
    }
}

// ---------------- adaLN combine: an = sigmoid(tg+bg)*lna + tk ---------------
__global__ void adaln_combine_kernel(const float* __restrict__ tgk,
                                     const float* __restrict__ bgv,
                                     float* __restrict__ outp)
{
    int i = blockIdx.x*256 + threadIdx.x;
    int r = i / CD, c = i - r*CD;
    float tg = tgk[(size_t)r*1536 + c];
    float tk = tgk[(size_t)r*1536 + 768 + c];
    outp[i] = sigm(tg + bgv[c])*g_lna[i] + tk;
}

// ---------------- pair-bias precompute: wgp, packed h-pairs, c1/c2 ----------
__global__ void pair_prep_kernel(const float* __restrict__ gp,
                                 const float* __restrict__ bp,
                                 const float* __restrict__ wp)
{
    int j = threadIdx.x;  // 128
    float wg[NH];
#pragma unroll
    for (int h=0; h<NH; h++){ wg[h] = gp[j]*wp[j*NH+h]; g_wgp[j*NH+h] = wg[h]; }
#pragma unroll
    for (int m=0; m<8; m++) g_wpk[m*CPD + j] = pk2(wg[2*m], wg[2*m+1]);
    __syncthreads();
    if (j < NH) {
        float c1=0.f, c2=0.f;
        for (int jj=0; jj<CPD; jj++){ c1 += bp[jj]*wp[jj*NH+j]; c2 += g_wgp[jj*NH+j]; }
        g_cc[j]=c1; g_cc[NH+j]=c2;
    }
}

// ---------------- pair bias v5: 256 threads, 2 pairs/thread -----------------
// Same dataflow as v3b but halved per-thread state (acc 32->16 regs) and
// doubled warps/CTA for latency hiding. Thread t owns pairs {t, t+256}.
#define PB_SMEM (512*36*4 + 128*8*8)
__global__ void __launch_bounds__(256) pair_bias_kernel(
    const float* __restrict__ pair, const float* __restrict__ beta)
{
    extern __shared__ __align__(16) float smem[];
    float* xs = smem;                         // [512][36]
    ull* wks = (ull*)(smem + 512*36);         // [128 k][8 m]
    __shared__ float csm[2*NH];

    int t = threadIdx.x;
    int q = blockIdx.x >> 1;
    int k0 = (blockIdx.x & 1) << 9;

    // stage weights transposed: wks[k][m] = g_wpk[m*128 + k]
    for (int i = t; i < 1024; i += 256) {
        int k = i >> 3, m = i & 7;
        wks[(k<<3) + m] = g_wpk[m*CPD + k];
    }
    if (t < 2*NH) csm[t] = g_cc[t];

    ull acc[2][8];
#pragma unroll
    for (int i=0;i<2;i++)
#pragma unroll
        for (int m=0;m<8;m++) acc[i][m]=0ull;
    float sm[2] = {0.f,0.f};
    float sq[2] = {0.f,0.f};

    const float* base = pair + (((size_t)q<<10) + k0)*CPD;

    for (int c = 0; c < 4; c++) {
        __syncthreads();
        // stage 512 rows x 32 cols (chunk c), coalesced float4
#pragma unroll
        for (int it=0; it<16; it++) {
            int g = (it<<8) + t;              // 0..4095 float4 slots
            int row = g >> 3, j = g & 7;
            *(float4*)(xs + row*36 + (j<<2)) =
                *(const float4*)(base + (size_t)row*CPD + (c<<5) + (j<<2));
        }
        __syncthreads();
#pragma unroll
        for (int kk=0; kk<32; kk++) {
            const ull* wr = wks + ((c<<5)+kk)*8;
            ull w0=wr[0], w1=wr[1], w2=wr[2], w3=wr[3];
            ull w4=wr[4], w5=wr[5], w6=wr[6], w7=wr[7];
#pragma unroll
            for (int i=0;i<2;i++){
                float xv = xs[(t + (i<<8))*36 + kk];
                sm[i] += xv;
                sq[i] = fmaf(xv, xv, sq[i]);
                ull xx = pk2(xv, xv);
                fma2(acc[i][0], xx, w0); fma2(acc[i][1], xx, w1);
                fma2(acc[i][2], xx, w2); fma2(acc[i][3], xx, w3);
                fma2(acc[i][4], xx, w4); fma2(acc[i][5], xx, w5);
                fma2(acc[i][6], xx, w6); fma2(acc[i][7], xx, w7);
            }
        }
    }

    // epilogue: 2 pairs, 16 heads each
#pragma unroll
    for (int i=0;i<2;i++){
        int p = t + (i<<8);
        int kk = k0 + p;
        float mu = sm[i]*(1.f/128.f);
        float rs = rsqrtf(sq[i]*(1.f/128.f) - mu*mu + 1e-5f);
        float murs = mu*rs;
        float bv = beta[((size_t)q<<10) + kk];
#pragma unroll
        for (int m=0;m<8;m++){
            float2 v = up2(acc[i][m]);
            int h0 = m<<1;
            float z0 = rs*v.x - murs*csm[NH+h0]   + csm[h0]   + bv;
            float z1 = rs*v.y - murs*csm[NH+h0+1] + csm[h0+1] + bv;
            g_bias[((size_t)h0<<20)     + ((size_t)q<<10) + kk] = z0;
            g_bias[((size_t)(h0+1)<<20) + ((size_t)q<<10) + kk] = z1;
        }
    }
}

// ---------------- flash attention (f32x2) + fused output gate (R9) ----------
__global__ void __launch_bounds__(128) attn_kernel(
    const float* __restrict__ qp, const float* __restrict__ kp,
    const float* __restrict__ vp, const float* __restrict__ gatep)
{
    __shared__ __align__(16) float pool[6144];
    __shared__ float Ms[64], Ls[64];
    int t = threadIdx.x;
    int half = t>>6, ql = t&63;
    int h = blockIdx.y;
    int qr = (blockIdx.x<<6) + ql;
    const float scale = 0.14433756729740643f;
    ull q2[24];
#pragma unroll
    for (int d4=0; d4<12; d4++){
        float4 qq = *(const float4*)(qp + (size_t)qr*3072 + h*48 + (d4<<2));
        q2[d4*2]   = pk2(qq.x*scale, qq.y*scale);
        q2[d4*2+1] = pk2(qq.z*scale, qq.w*scale);
    }
    float m = -1e30f, l = 0.f;
    ull acc2[24];
#pragma unroll
    for (int i=0;i<24;i++) acc2[i]=0ull;
    int kb = half<<9;
    const float* brow = g_bias + ((size_t)h<<20) + ((size_t)qr<<10) + kb;
    for (int kt=0; kt<512; kt+=32) {
        __syncthreads();
#pragma unroll
        for (int it=0; it<6; it++) {
            int i4 = t + (it<<7);
            int d4 = i4 % 12;
            int rem = i4 / 12;
            int j = rem & 31, hh = rem >> 5;
            int krow = (hh<<9) + kt + j;
            ((float4*)pool)[i4]      = *(const float4*)(kp + (size_t)krow*3072 + h*48 + (d4<<2));
            ((float4*)pool)[768+i4]  = *(const float4*)(vp + (size_t)krow*3072 + h*48 + (d4<<2));
        }
        __syncthreads();
        float bb[32];
#pragma unroll
        for (int i=0;i<8;i++){
            float4 b4 = *(const float4*)(brow + kt + (i<<2));
            bb[i*4]=b4.x; bb[i*4+1]=b4.y; bb[i*4+2]=b4.z; bb[i*4+3]=b4.w;
        }
        const float* Kt = pool + half*1536;
        const float* Vt = pool + 3072 + half*1536;
        for (int j=0; j<32; j++) {
            const ull* kr2 = (const ull*)(Kt + j*48);
            ull d2 = 0ull;
#pragma unroll
            for (int i=0;i<24;i++) fma2(d2, q2[i], kr2[i]);
            float2 dd = up2(d2);
            float sc = dd.x + dd.y + bb[j];
            if (sc > m) {
                float corr = __expf(m - sc);
                l *= corr;
                ull cp = pk2(corr, corr);
#pragma unroll
                for (int i=0;i<24;i++) acc2[i] = mul2(acc2[i], cp);
                m = sc;
            }
            float pw = __expf(sc - m);
            l += pw;
            ull pp = pk2(pw, pw);
            const ull* vr2 = (const ull*)(Vt + j*48);
#pragma unroll
            for (int i=0;i<24;i++) fma2(acc2[i], pp, vr2[i]);
        }
    }
    __syncthreads();
    if (half == 1) {
        Ms[ql]=m; Ls[ql]=l;
#pragma unroll
        for (int i=0;i<24;i++){
            float2 v = up2(acc2[i]);
            pool[ql*48+2*i]=v.x; pool[ql*48+2*i+1]=v.y;
        }
    }
    __syncthreads();
    if (half == 0) {
        float m2=Ms[ql], l2=Ls[ql];
        float mn=fmaxf(m,m2);
        float c1=__expf(m-mn), c2=__expf(m2-mn);
        float inv=1.f/(l*c1 + l2*c2);
#pragma unroll
        for (int i=0;i<24;i++){
            float2 v = up2(acc2[i]);
            float g0 = sigm(gatep[(size_t)qr*3072 + h*48 + 2*i]);
            float g1 = sigm(gatep[(size_t)qr*3072 + h*48 + 2*i+1]);
            g_o[(size_t)qr*CD + h*48 + 2*i]   = (v.x*c1 + pool[ql*48+2*i]*c2)*inv*g0;
            g_o[(size_t)qr*CD + h*48 + 2*i+1] = (v.y*c1 + pool[ql*48+2*i+1]*c2)*inv*g1;
        }
    }
}

// ---------------- small elementwise kernels ---------------------------------
__global__ void bout_kernel(const float* __restrict__ bso) {
    int i = blockIdx.x*256 + threadIdx.x;
    int r = i / CD, c = i - r*CD;
    float att = g_attout[i] + g_attout[NT*CD + i];
    g_bout[i] = sigm(g_ts2[(size_t)r*1536 + c] + bso[c])*att;
}
__global__ void swiglu_kernel() {
    int i = blockIdx.x*256 + threadIdx.x;
    int r = i / HD, c = i - r*HD;
    float x = g_h12[(size_t)r*3072 + c];
    float y = g_h12[(size_t)r*3072 + 1536 + c];
    g_h1[i] = x*sigm(x)*y;
}
__global__ void final_kernel(const float* __restrict__ bs2, float* __restrict__ outp) {
    int i = blockIdx.x*256 + threadIdx.x;
    int r = i / CD, c = i - r*CD;
    float t3 = g_t3[i] + g_t3[NT*CD + i];
    outp[i] = g_bout[i] + sigm(g_ts2[(size_t)r*1536 + 768 + c] + bs2[c])*t3;
}

// ---------------- launch: dual-stream overlap (exact R11 schedule) ----------
extern "C" void kernel_launch(void* const* d_in, const int* in_sizes, int n_in,
                              void* d_out, int out_size)
{
    (void)in_sizes; (void)n_in; (void)out_size;
    const float* a     = (const float*)d_in[0];
    const float* s     = (const float*)d_in[1];
    const float* pair  = (const float*)d_in[2];
    const float* beta  = (const float*)d_in[3];
    const float* sg1   = (const float*)d_in[4];
    const float* wg1   = (const float*)d_in[5];
    const float* bg1   = (const float*)d_in[6];
    const float* wsk1  = (const float*)d_in[7];
    const float* wq    = (const float*)d_in[8];
    const float* bq    = (const float*)d_in[9];
    const float* wk    = (const float*)d_in[10];
    const float* wv    = (const float*)d_in[11];
    const float* gp    = (const float*)d_in[12];
    const float* bp    = (const float*)d_in[13];
    const float* wp    = (const float*)d_in[14];
    const float* wgate = (const float*)d_in[15];
    const float* wo    = (const float*)d_in[16];
    const float* wso   = (const float*)d_in[17];
    const float* bso   = (const float*)d_in[18];
    const float* sg2   = (const float*)d_in[19];
    const float* wg2   = (const float*)d_in[20];
    const float* bg2   = (const float*)d_in[21];
    const float* wsk2  = (const float*)d_in[22];
    const float* w1    = (const float*)d_in[23];
    const float* w2    = (const float*)d_in[24];
    const float* w3    = (const float*)d_in[25];
    const float* ws2   = (const float*)d_in[26];
    const float* bs2   = (const float*)d_in[27];

    float *p_sn1,*p_sn2,*p_an,*p_an2,*p_o,*p_attout,*p_h1,*p_t3,*p_tgk,*p_tgk2,
          *p_qkvg,*p_ts2,*p_h12,*p_bqkv;
    cudaGetSymbolAddress((void**)&p_sn1,   g_sn1);
    cudaGetSymbolAddress((void**)&p_sn2,   g_sn2);
    cudaGetSymbolAddress((void**)&p_an,    g_an);
    cudaGetSymbolAddress((void**)&p_an2,   g_an2);
    cudaGetSymbolAddress((void**)&p_o,     g_o);
    cudaGetSymbolAddress((void**)&p_attout,g_attout);
    cudaGetSymbolAddress((void**)&p_h1,    g_h1);
    cudaGetSymbolAddress((void**)&p_t3,    g_t3);
    cudaGetSymbolAddress((void**)&p_tgk,   g_tgk);
    cudaGetSymbolAddress((void**)&p_tgk2,  g_tgk2);
    cudaGetSymbolAddress((void**)&p_qkvg,  g_qkvg);
    cudaGetSymbolAddress((void**)&p_ts2,   g_ts2);
    cudaGetSymbolAddress((void**)&p_h12,   g_h12);
    cudaGetSymbolAddress((void**)&p_bqkv,  g_bqkv);

    static cudaStream_t s1 = nullptr;
    static cudaEvent_t eFork, ePair, eTs2, eT3;
    if (!s1) {
        cudaFuncSetAttribute(pair_bias_kernel,
                             cudaFuncAttributeMaxDynamicSharedMemorySize, PB_SMEM);
        cudaStreamCreateWithFlags(&s1, cudaStreamNonBlocking);
        cudaEventCreateWithFlags(&eFork, cudaEventDisableTiming);
        cudaEventCreateWithFlags(&ePair, cudaEventDisableTiming);
        cudaEventCreateWithFlags(&eTs2,  cudaEventDisableTiming);
        cudaEventCreateWithFlags(&eT3,   cudaEventDisableTiming);
    }

    // ---- prep (legacy stream) ----
    ln_kernel<<<NT, 256>>>(a, s, sg1, sg2);
    pair_prep_kernel<<<1, 128>>>(gp, bp, wp);
    bfill_kernel<<<12, 256>>>(bq);

    // ---- fork: s1 carries pair_bias + ts2 + transition chain ----
    cudaEventRecord(eFork, 0);
    cudaStreamWaitEvent(s1, eFork, 0);

    pair_bias_kernel<<<2048, 256, PB_SMEM, s1>>>(pair, beta);
    cudaEventRecord(ePair, s1);
    sgemm64_kernel<<<dim3(24,16,1), 64, 0, s1>>>(s, CD, wso, ws2, wso, wso, CD,
                                                 nullptr, p_ts2, 1536, CD, 0);
    cudaEventRecord(eTs2, s1);
    sgemm64_kernel<<<dim3(24,16,1), 64, 0, s1>>>(p_sn2, CD, wg2, wsk2, wg2, wg2, CD,
                                                 nullptr, p_tgk2, 1536, CD, 0);
    adaln_combine_kernel<<<NT*CD/256, 256, 0, s1>>>(p_tgk2, bg2, p_an2);
    sgemm64_kernel<<<dim3(48,16,1), 64, 0, s1>>>(p_an2, CD, w1, w2, w1, w1, HD,
                                                 nullptr, p_h12, 3072, CD, 0);
    swiglu_kernel<<<NT*HD/256, 256, 0, s1>>>();
    sgemm64_kernel<<<dim3(12,16,2), 64, 0, s1>>>(p_h1, HD, w3, w3, w3, w3, CD,
                                                 nullptr, p_t3, CD, CD, NT*CD);
    cudaEventRecord(eT3, s1);

    // ---- legacy stream: attention chain ----
    sgemm64_kernel<<<dim3(24,16,1), 64>>>(p_sn1, CD, wg1, wsk1, wg1, wg1, CD,
                                          nullptr, p_tgk, 1536, CD, 0);
    adaln_combine_kernel<<<NT*CD/256, 256>>>(p_tgk, bg1, p_an);
    sgemm64_kernel<<<dim3(48,16,1), 64>>>(p_an, CD, wq, wk, wv, wgate, CD,
                                          p_bqkv, p_qkvg, 3072, CD, 0);
    cudaStreamWaitEvent(0, ePair, 0);
    attn_kernel<<<dim3(16, 16), 128>>>(p_qkvg, p_qkvg + 768, p_qkvg + 1536, p_qkvg + 2304);
    sgemm64_kernel<<<dim3(12,16,2), 64>>>(p_o, CD, wo, wo, wo, wo, CD,
                                          nullptr, p_attout, CD, 384, NT*CD);
    cudaStreamWaitEvent(0, eTs2, 0);
    bout_kernel<<<NT*CD/256, 256>>>(bso);
    cudaStreamWaitEvent(0, eT3, 0);       // join s1 back before final
    final_kernel<<<NT*CD/256, 256>>>(bs2, (float*)d_out);
}

// round 15
// speedup vs baseline: 1.0309x; 1.0043x over previous
#include <cuda_runtime.h>
#include <cstdint>
#include <math.h>

#define NT 1024
#define CD 768
#define NH 16
#define DH 48
#define HD 1536
#define CPD 128

typedef unsigned long long ull;

// ---------------- f32x2 packed-math helpers (sm_100+) -----------------------
__device__ __forceinline__ ull pk2(float lo, float hi) {
    ull r; asm("mov.b64 %0, {%1, %2};" : "=l"(r) : "f"(lo), "f"(hi)); return r;
}
__device__ __forceinline__ void fma2(ull &d, ull a, ull b) {
    asm("fma.rn.f32x2 %0, %1, %2, %0;" : "+l"(d) : "l"(a), "l"(b));
}
__device__ __forceinline__ ull add2(ull a, ull b) {
    ull r; asm("add.rn.f32x2 %0, %1, %2;" : "=l"(r) : "l"(a), "l"(b)); return r;
}
__device__ __forceinline__ ull mul2(ull a, ull b) {
    ull r; asm("mul.rn.f32x2 %0, %1, %2;" : "=l"(r) : "l"(a), "l"(b)); return r;
}
__device__ __forceinline__ float2 up2(ull v) {
    float2 r; asm("mov.b64 {%0, %1}, %2;" : "=f"(r.x), "=f"(r.y) : "l"(v)); return r;
}
__device__ __forceinline__ float sigm(float x) { return 1.f/(1.f+__expf(-x)); }

// ---------------- scratch (device globals; no allocations allowed) ----------
__device__ __align__(16) float g_lna[NT*CD];
__device__ __align__(16) float g_sn1[NT*CD];
__device__ __align__(16) float g_sn2[NT*CD];
__device__ __align__(16) float g_an[NT*CD];
__device__ __align__(16) float g_an2[NT*CD];
__device__ __align__(16) float g_o[NT*CD];
__device__ __align__(16) float g_attout[2*NT*CD];    // split-K partials
__device__ __align__(16) float g_bout[NT*CD];
__device__ __align__(16) float g_h1[NT*HD];
__device__ __align__(16) float g_t3[2*NT*CD];        // split-K partials
__device__ __align__(16) float g_tgk[NT*2*CD];       // attn adaLN tg|tk, stride 1536
__device__ __align__(16) float g_tgk2[NT*2*CD];      // transition adaLN tg|tk
__device__ __align__(16) float g_qkvg[NT*4*CD];      // q|k|v|gate, stride 3072
__device__ __align__(16) float g_ts2[NT*2*CD];       // s@wso | s@ws2, stride 1536
__device__ __align__(16) float g_h12[NT*2*HD];       // h1|h2, stride 3072
__device__ __align__(16) float g_bqkv[4*CD];
__device__ __align__(16) float g_wgp[CPD*NH];
__device__ __align__(16) ull   g_wpk[8*CPD];         // packed h-pairs
__device__ __align__(16) float g_cc[2*NH];
__device__ __align__(16) float g_bias[(size_t)NH*NT*NT];   // 64 MB [h][q][k]

// ---------------- LayerNorm of a and s; sn1 = LN(s)*sg1, sn2 = LN(s)*sg2 ----
__global__ void ln_kernel(const float* __restrict__ a, const float* __restrict__ s,
                          const float* __restrict__ sg1, const float* __restrict__ sg2)
{
    int r = blockIdx.x, t = threadIdx.x;
    const float* ar = a + (size_t)r*CD;
    const float* sr = s + (size_t)r*CD;
    float va[3], vs[3];
    float s0=0.f,s1=0.f,s2=0.f,s3=0.f;
#pragma unroll
    for (int i=0;i<3;i++){
        va[i]=ar[t+256*i]; vs[i]=sr[t+256*i];
        s0+=va[i]; s1+=va[i]*va[i]; s2+=vs[i]; s3+=vs[i]*vs[i];
    }
    __shared__ float red[4][8];
    int lane=t&31, w=t>>5;
#pragma unroll
    for (int o=16;o;o>>=1){
        s0+=__shfl_xor_sync(0xffffffffu,s0,o);
        s1+=__shfl_xor_sync(0xffffffffu,s1,o);
        s2+=__shfl_xor_sync(0xffffffffu,s2,o);
        s3+=__shfl_xor_sync(0xffffffffu,s3,o);
    }
    if (lane==0){ red[0][w]=s0; red[1][w]=s1; red[2][w]=s2; red[3][w]=s3; }
    __syncthreads();
    float S0=0.f,S1=0.f,S2=0.f,S3=0.f;
#pragma unroll
    for (int i=0;i<8;i++){ S0+=red[0][i]; S1+=red[1][i]; S2+=red[2][i]; S3+=red[3][i]; }
    float mua=S0*(1.f/768.f), rsa=rsqrtf(S1*(1.f/768.f)-mua*mua+1e-5f);
    float mus=S2*(1.f/768.f), rss=rsqrtf(S3*(1.f/768.f)-mus*mus+1e-5f);
#pragma unroll
    for (int i=0;i<3;i++){
        int c=t+256*i; size_t idx=(size_t)r*CD+c;
        g_lna[idx]=(va[i]-mua)*rsa;
        float sv=(vs[i]-mus)*rss;
        g_sn1[idx]=sv*sg1[c];
        g_sn2[idx]=sv*sg2[c];
    }
}

__global__ void bfill_kernel(const float* __restrict__ bq)
{
    int i = blockIdx.x*256 + threadIdx.x;
    g_bqkv[i] = (i < CD) ? bq[i] : 0.f;
}

// ---------------- SGEMM: 64x64 tile, 64 threads, 8x8/thread, f32x2 (R9) -----
__global__ void __launch_bounds__(64) sgemm64_kernel(
    const float* __restrict__ A, int lda,
    const float* __restrict__ B0, const float* __restrict__ B1,
    const float* __restrict__ B2, const float* __restrict__ B3,
    int bN, const float* __restrict__ biasv,
    float* __restrict__ C, int Nn, int K, int cz)
{
    __shared__ __align__(16) float As[2][8][64];
    __shared__ __align__(16) float Bs[2][8][64];
    int t = threadIdx.x;
    int z = blockIdx.z;
    int tx = t & 7, ty = t >> 3;
    int row0 = blockIdx.y << 6;
    int cb = blockIdx.x;
    int perSrc = bN >> 6;
    int si = cb / perSrc;
    const float* Bsel = (si==0) ? B0 : (si==1) ? B1 : (si==2) ? B2 : B3;
    int colSrc = (cb - si*perSrc) << 6;

    const float* Ag = A + (size_t)(row0 + t)*lda + (size_t)z*K;
    const float* Bg = Bsel + (size_t)z*K*bN + (size_t)(t>>3)*bN + colSrc + ((t&7)<<2);
    C += (size_t)z*cz;

    ull acc[8][4];
#pragma unroll
    for (int i=0;i<8;i++)
#pragma unroll
        for (int j=0;j<4;j++) acc[i][j]=0ull;

    int nt = K >> 3;
    float4 a0 = *(const float4*)(Ag);
    float4 a1 = *(const float4*)(Ag + 4);
    float4 b0 = *(const float4*)(Bg);
    float4 b1 = *(const float4*)(Bg + 32);
    {
        As[0][0][t]=a0.x; As[0][1][t]=a0.y; As[0][2][t]=a0.z; As[0][3][t]=a0.w;
        As[0][4][t]=a1.x; As[0][5][t]=a1.y; As[0][6][t]=a1.z; As[0][7][t]=a1.w;
        *(float4*)&Bs[0][t>>3][(t&7)<<2] = b0;
        *(float4*)&Bs[0][t>>3][((t&7)<<2)+32] = b1;
    }
    __syncthreads();

    for (int kt = 0; kt < nt; kt++) {
        int cur = kt & 1;
        bool more = (kt+1) < nt;
        if (more) {
            a0 = *(const float4*)(Ag + (kt+1)*8);
            a1 = *(const float4*)(Ag + (kt+1)*8 + 4);
            b0 = *(const float4*)(Bg + (size_t)(kt+1)*8*bN);
            b1 = *(const float4*)(Bg + (size_t)(kt+1)*8*bN + 32);
        }
#pragma unroll
        for (int kk = 0; kk < 8; kk++) {
            float4 av0 = *(const float4*)&As[cur][kk][ty<<3];
            float4 av1 = *(const float4*)&As[cur][kk][(ty<<3)+4];
            float4 bv0 = *(const float4*)&Bs[cur][kk][tx<<3];
            float4 bv1 = *(const float4*)&Bs[cur][kk][(tx<<3)+4];
            ull bp0 = pk2(bv0.x,bv0.y), bp1 = pk2(bv0.z,bv0.w);
            ull bp2 = pk2(bv1.x,bv1.y), bp3 = pk2(bv1.z,bv1.w);
            float aarr[8] = {av0.x,av0.y,av0.z,av0.w,av1.x,av1.y,av1.z,av1.w};
#pragma unroll
            for (int i=0;i<8;i++){
                ull aa = pk2(aarr[i], aarr[i]);
                fma2(acc[i][0], aa, bp0);
                fma2(acc[i][1], aa, bp1);
                fma2(acc[i][2], aa, bp2);
                fma2(acc[i][3], aa, bp3);
            }
        }
        if (more) {
            int nx = cur ^ 1;
            As[nx][0][t]=a0.x; As[nx][1][t]=a0.y; As[nx][2][t]=a0.z; As[nx][3][t]=a0.w;
            As[nx][4][t]=a1.x; As[nx][5][t]=a1.y; As[nx][6][t]=a1.z; As[nx][7][t]=a1.w;
            *(float4*)&Bs[nx][t>>3][(t&7)<<2] = b0;
            *(float4*)&Bs[nx][t>>3][((t&7)<<2)+32] = b1;
            __syncthreads();
        }
    }

    int col = (cb<<6) + (tx<<3);
    float4 bb0 = make_float4(0.f,0.f,0.f,0.f), bb1 = bb0;
    if (biasv) { bb0 = *(const float4*)(biasv + col); bb1 = *(const float4*)(biasv + col + 4); }
#pragma unroll
    for (int i=0;i<8;i++){
        int r = row0 + (ty<<3) + i;
        float2 p0=up2(acc[i][0]), p1=up2(acc[i][1]), p2=up2(acc[i][2]), p3=up2(acc[i][3]);
        float4 o0 = make_float4(p0.x+bb0.x, p0.y+bb0.y, p1.x+bb0.z, p1.y+bb0.w);
        float4 o1 = make_float4(p2.x+bb1.x, p2.y+bb1.y, p3.x+bb1.z, p3.y+bb1.w);
        *(float4*)(C + (size_t)r*Nn + col) = o0;
        *(float4*)(C + (size_t)r*Nn + col + 4) = o1;
    }
}

// ---------------- adaLN combine: an = sigmoid(tg+bg)*lna + tk ---------------
__global__ void adaln_combine_kernel(const float* __restrict__ tgk,
                                     const float* __restrict__ bgv,
                                     float* __restrict__ outp)
{
    int i = blockIdx.x*256 + threadIdx.x;
    int r = i / CD, c = i - r*CD;
    float tg = tgk[(size_t)r*1536 + c];
    float tk = tgk[(size_t)r*1536 + 768 + c];
    outp[i] = sigm(tg + bgv[c])*g_lna[i] + tk;
}

// ---------------- pair-bias precompute: wgp, packed h-pairs, c1/c2 ----------
__global__ void pair_prep_kernel(const float* __restrict__ gp,
                                 const float* __restrict__ bp,
                                 const float* __restrict__ wp)
{
    int j = threadIdx.x;  // 128
    float wg[NH];
#pragma unroll
    for (int h=0; h<NH; h++){ wg[h] = gp[j]*wp[j*NH+h]; g_wgp[j*NH+h] = wg[h]; }
#pragma unroll
    for (int m=0; m<8; m++) g_wpk[m*CPD + j] = pk2(wg[2*m], wg[2*m+1]);
    __syncthreads();
    if (j < NH) {
        float c1=0.f, c2=0.f;
        for (int jj=0; jj<CPD; jj++){ c1 += bp[jj]*wp[jj*NH+j]; c2 += g_wgp[jj*NH+j]; }
        g_cc[j]=c1; g_cc[NH+j]=c2;
    }
}

// ---------------- pair bias v6: 256 pairs/block, 1 pair/thread, LDS.128 -----
// grid 4096 = (q, k-quarter). 44KB smem -> 4 CTAs/SM (occ ~50%). Weights read
// as broadcast ulonglong2 (4 LDS.128 per k, shared by whole warp).
#define PB_SMEM (256*36*4 + 128*8*8)
__global__ void __launch_bounds__(256) pair_bias_kernel(
    const float* __restrict__ pair, const float* __restrict__ beta)
{
    extern __shared__ __align__(16) float smem[];
    float* xs = smem;                         // [256][36]
    ull* wks = (ull*)(smem + 256*36);         // [128 k][8 m]
    __shared__ float csm[2*NH];

    int t = threadIdx.x;
    int q = blockIdx.x >> 2;
    int k0 = (blockIdx.x & 3) << 8;           // 0,256,512,768

    // stage weights transposed: wks[k][m] = g_wpk[m*128 + k]
    for (int i = t; i < 1024; i += 256) {
        int k = i >> 3, m = i & 7;
        wks[(k<<3) + m] = g_wpk[m*CPD + k];
    }
    if (t < 2*NH) csm[t] = g_cc[t];

    ull acc[8];
#pragma unroll
    for (int m=0;m<8;m++) acc[m]=0ull;
    float sm = 0.f, sq = 0.f;

    const float* base = pair + (((size_t)q<<10) + k0)*CPD;

    for (int c = 0; c < 4; c++) {
        __syncthreads();
        // stage 256 rows x 32 cols (chunk c), coalesced float4
#pragma unroll
        for (int it=0; it<8; it++) {
            int g = (it<<8) + t;              // 0..2047 float4 slots
            int row = g >> 3, j = g & 7;
            *(float4*)(xs + row*36 + (j<<2)) =
                *(const float4*)(base + (size_t)row*CPD + (c<<5) + (j<<2));
        }
        __syncthreads();
        const float* xrow = xs + t*36;
#pragma unroll
        for (int kk=0; kk<32; kk++) {
            const ulonglong2* wr = (const ulonglong2*)(wks + ((c<<5)+kk)*8);
            ulonglong2 w01 = wr[0];
            ulonglong2 w23 = wr[1];
            ulonglong2 w45 = wr[2];
            ulonglong2 w67 = wr[3];
            float xv = xrow[kk];
            sm += xv;
            sq = fmaf(xv, xv, sq);
            ull xx = pk2(xv, xv);
            fma2(acc[0], xx, w01.x); fma2(acc[1], xx, w01.y);
            fma2(acc[2], xx, w23.x); fma2(acc[3], xx, w23.y);
            fma2(acc[4], xx, w45.x); fma2(acc[5], xx, w45.y);
            fma2(acc[6], xx, w67.x); fma2(acc[7], xx, w67.y);
        }
    }

    // epilogue: one pair, 16 heads
    {
        int kk = k0 + t;
        float mu = sm*(1.f/128.f);
        float rs = rsqrtf(sq*(1.f/128.f) - mu*mu + 1e-5f);
        float murs = mu*rs;
        float bv = beta[((size_t)q<<10) + kk];
#pragma unroll
        for (int m=0;m<8;m++){
            float2 v = up2(acc[m]);
            int h0 = m<<1;
            float z0 = rs*v.x - murs*csm[NH+h0]   + csm[h0]   + bv;
            float z1 = rs*v.y - murs*csm[NH+h0+1] + csm[h0+1] + bv;
            g_bias[((size_t)h0<<20)     + ((size_t)q<<10) + kk] = z0;
            g_bias[((size_t)(h0+1)<<20) + ((size_t)q<<10) + kk] = z1;
        }
    }
}

// ---------------- flash attention (f32x2) + fused output gate (R9) ----------
__global__ void __launch_bounds__(128) attn_kernel(
    const float* __restrict__ qp, const float* __restrict__ kp,
    const float* __restrict__ vp, const float* __restrict__ gatep)
{
    __shared__ __align__(16) float pool[6144];
    __shared__ float Ms[64], Ls[64];
    int t = threadIdx.x;
    int half = t>>6, ql = t&63;
    int h = blockIdx.y;
    int qr = (blockIdx.x<<6) + ql;
    const float scale = 0.14433756729740643f;
    ull q2[24];
#pragma unroll
    for (int d4=0; d4<12; d4++){
        float4 qq = *(const float4*)(qp + (size_t)qr*3072 + h*48 + (d4<<2));
        q2[d4*2]   = pk2(qq.x*scale, qq.y*scale);
        q2[d4*2+1] = pk2(qq.z*scale, qq.w*scale);
    }
    float m = -1e30f, l = 0.f;
    ull acc2[24];
#pragma unroll
    for (int i=0;i<24;i++) acc2[i]=0ull;
    int kb = half<<9;
    const float* brow = g_bias + ((size_t)h<<20) + ((size_t)qr<<10) + kb;
    for (int kt=0; kt<512; kt+=32) {
        __syncthreads();
#pragma unroll
        for (int it=0; it<6; it++) {
            int i4 = t + (it<<7);
            int d4 = i4 % 12;
            int rem = i4 / 12;
            int j = rem & 31, hh = rem >> 5;
            int krow = (hh<<9) + kt + j;
            ((float4*)pool)[i4]      = *(const float4*)(kp + (size_t)krow*3072 + h*48 + (d4<<2));
            ((float4*)pool)[768+i4]  = *(const float4*)(vp + (size_t)krow*3072 + h*48 + (d4<<2));
        }
        __syncthreads();
        float bb[32];
#pragma unroll
        for (int i=0;i<8;i++){
            float4 b4 = *(const float4*)(brow + kt + (i<<2));
            bb[i*4]=b4.x; bb[i*4+1]=b4.y; bb[i*4+2]=b4.z; bb[i*4+3]=b4.w;
        }
        const float* Kt = pool + half*1536;
        const float* Vt = pool + 3072 + half*1536;
        for (int j=0; j<32; j++) {
            const ull* kr2 = (const ull*)(Kt + j*48);
            ull d2 = 0ull;
#pragma unroll
            for (int i=0;i<24;i++) fma2(d2, q2[i], kr2[i]);
            float2 dd = up2(d2);
            float sc = dd.x + dd.y + bb[j];
            if (sc > m) {
                float corr = __expf(m - sc);
                l *= corr;
                ull cp = pk2(corr, corr);
#pragma unroll
                for (int i=0;i<24;i++) acc2[i] = mul2(acc2[i], cp);
                m = sc;
            }
            float pw = __expf(sc - m);
            l += pw;
            ull pp = pk2(pw, pw);
            const ull* vr2 = (const ull*)(Vt + j*48);
#pragma unroll
            for (int i=0;i<24;i++) fma2(acc2[i], pp, vr2[i]);
        }
    }
    __syncthreads();
    if (half == 1) {
        Ms[ql]=m; Ls[ql]=l;
#pragma unroll
        for (int i=0;i<24;i++){
            float2 v = up2(acc2[i]);
            pool[ql*48+2*i]=v.x; pool[ql*48+2*i+1]=v.y;
        }
    }
    __syncthreads();
    if (half == 0) {
        float m2=Ms[ql], l2=Ls[ql];
        float mn=fmaxf(m,m2);
        float c1=__expf(m-mn), c2=__expf(m2-mn);
        float inv=1.f/(l*c1 + l2*c2);
#pragma unroll
        for (int i=0;i<24;i++){
            float2 v = up2(acc2[i]);
            float g0 = sigm(gatep[(size_t)qr*3072 + h*48 + 2*i]);
            float g1 = sigm(gatep[(size_t)qr*3072 + h*48 + 2*i+1]);
            g_o[(size_t)qr*CD + h*48 + 2*i]   = (v.x*c1 + pool[ql*48+2*i]*c2)*inv*g0;
            g_o[(size_t)qr*CD + h*48 + 2*i+1] = (v.y*c1 + pool[ql*48+2*i+1]*c2)*inv*g1;
        }
    }
}

// ---------------- small elementwise kernels ---------------------------------
__global__ void bout_kernel(const float* __restrict__ bso) {
    int i = blockIdx.x*256 + threadIdx.x;
    int r = i / CD, c = i - r*CD;
    float att = g_attout[i] + g_attout[NT*CD + i];
    g_bout[i] = sigm(g_ts2[(size_t)r*1536 + c] + bso[c])*att;
}
__global__ void swiglu_kernel() {
    int i = blockIdx.x*256 + threadIdx.x;
    int r = i / HD, c = i - r*HD;
    float x = g_h12[(size_t)r*3072 + c];
    float y = g_h12[(size_t)r*3072 + 1536 + c];
    g_h1[i] = x*sigm(x)*y;
}
__global__ void final_kernel(const float* __restrict__ bs2, float* __restrict__ outp) {
    int i = blockIdx.x*256 + threadIdx.x;
    int r = i / CD, c = i - r*CD;
    float t3 = g_t3[i] + g_t3[NT*CD + i];
    outp[i] = g_bout[i] + sigm(g_ts2[(size_t)r*1536 + 768 + c] + bs2[c])*t3;
}

// ---------------- launch: dual-stream overlap (exact R11 schedule) ----------
extern "C" void kernel_launch(void* const* d_in, const int* in_sizes, int n_in,
                              void* d_out, int out_size)
{
    (void)in_sizes; (void)n_in; (void)out_size;
    const float* a     = (const float*)d_in[0];
    const float* s     = (const float*)d_in[1];
    const float* pair  = (const float*)d_in[2];
    const float* beta  = (const float*)d_in[3];
    const float* sg1   = (const float*)d_in[4];
    const float* wg1   = (const float*)d_in[5];
    const float* bg1   = (const float*)d_in[6];
    const float* wsk1  = (const float*)d_in[7];
    const float* wq    = (const float*)d_in[8];
    const float* bq    = (const float*)d_in[9];
    const float* wk    = (const float*)d_in[10];
    const float* wv    = (const float*)d_in[11];
    const float* gp    = (const float*)d_in[12];
    const float* bp    = (const float*)d_in[13];
    const float* wp    = (const float*)d_in[14];
    const float* wgate = (const float*)d_in[15];
    const float* wo    = (const float*)d_in[16];
    const float* wso   = (const float*)d_in[17];
    const float* bso   = (const float*)d_in[18];
    const float* sg2   = (const float*)d_in[19];
    const float* wg2   = (const float*)d_in[20];
    const float* bg2   = (const float*)d_in[21];
    const float* wsk2  = (const float*)d_in[22];
    const float* w1    = (const float*)d_in[23];
    const float* w2    = (const float*)d_in[24];
    const float* w3    = (const float*)d_in[25];
    const float* ws2   = (const float*)d_in[26];
    const float* bs2   = (const float*)d_in[27];

    float *p_sn1,*p_sn2,*p_an,*p_an2,*p_o,*p_attout,*p_h1,*p_t3,*p_tgk,*p_tgk2,
          *p_qkvg,*p_ts2,*p_h12,*p_bqkv;
    cudaGetSymbolAddress((void**)&p_sn1,   g_sn1);
    cudaGetSymbolAddress((void**)&p_sn2,   g_sn2);
    cudaGetSymbolAddress((void**)&p_an,    g_an);
    cudaGetSymbolAddress((void**)&p_an2,   g_an2);
    cudaGetSymbolAddress((void**)&p_o,     g_o);
    cudaGetSymbolAddress((void**)&p_attout,g_attout);
    cudaGetSymbolAddress((void**)&p_h1,    g_h1);
    cudaGetSymbolAddress((void**)&p_t3,    g_t3);
    cudaGetSymbolAddress((void**)&p_tgk,   g_tgk);
    cudaGetSymbolAddress((void**)&p_tgk2,  g_tgk2);
    cudaGetSymbolAddress((void**)&p_qkvg,  g_qkvg);
    cudaGetSymbolAddress((void**)&p_ts2,   g_ts2);
    cudaGetSymbolAddress((void**)&p_h12,   g_h12);
    cudaGetSymbolAddress((void**)&p_bqkv,  g_bqkv);

    static cudaStream_t s1 = nullptr;
    static cudaEvent_t eFork, ePair, eTs2, eT3;
    if (!s1) {
        cudaFuncSetAttribute(pair_bias_kernel,
                             cudaFuncAttributeMaxDynamicSharedMemorySize, PB_SMEM);
        cudaStreamCreateWithFlags(&s1, cudaStreamNonBlocking);
        cudaEventCreateWithFlags(&eFork, cudaEventDisableTiming);
        cudaEventCreateWithFlags(&ePair, cudaEventDisableTiming);
        cudaEventCreateWithFlags(&eTs2,  cudaEventDisableTiming);
        cudaEventCreateWithFlags(&eT3,   cudaEventDisableTiming);
    }

    // ---- prep (legacy stream) ----
    ln_kernel<<<NT, 256>>>(a, s, sg1, sg2);
    pair_prep_kernel<<<1, 128>>>(gp, bp, wp);
    bfill_kernel<<<12, 256>>>(bq);

    // ---- fork: s1 carries pair_bias + ts2 + transition chain ----
    cudaEventRecord(eFork, 0);
    cudaStreamWaitEvent(s1, eFork, 0);

    pair_bias_kernel<<<4096, 256, PB_SMEM, s1>>>(pair, beta);
    cudaEventRecord(ePair, s1);
    sgemm64_kernel<<<dim3(24,16,1), 64, 0, s1>>>(s, CD, wso, ws2, wso, wso, CD,
                                                 nullptr, p_ts2, 1536, CD, 0);
    cudaEventRecord(eTs2, s1);
    sgemm64_kernel<<<dim3(24,16,1), 64, 0, s1>>>(p_sn2, CD, wg2, wsk2, wg2, wg2, CD,
                                                 nullptr, p_tgk2, 1536, CD, 0);
    adaln_combine_kernel<<<NT*CD/256, 256, 0, s1>>>(p_tgk2, bg2, p_an2);
    sgemm64_kernel<<<dim3(48,16,1), 64, 0, s1>>>(p_an2, CD, w1, w2, w1, w1, HD,
                                                 nullptr, p_h12, 3072, CD, 0);
    swiglu_kernel<<<NT*HD/256, 256, 0, s1>>>();
    sgemm64_kernel<<<dim3(12,16,2), 64, 0, s1>>>(p_h1, HD, w3, w3, w3, w3, CD,
                                                 nullptr, p_t3, CD, CD, NT*CD);
    cudaEventRecord(eT3, s1);

    // ---- legacy stream: attention chain ----
    sgemm64_kernel<<<dim3(24,16,1), 64>>>(p_sn1, CD, wg1, wsk1, wg1, wg1, CD,
                                          nullptr, p_tgk, 1536, CD, 0);
    adaln_combine_kernel<<<NT*CD/256, 256>>>(p_tgk, bg1, p_an);
    sgemm64_kernel<<<dim3(48,16,1), 64>>>(p_an, CD, wq, wk, wv, wgate, CD,
                                          p_bqkv, p_qkvg, 3072, CD, 0);
    cudaStreamWaitEvent(0, ePair, 0);
    attn_kernel<<<dim3(16, 16), 128>>>(p_qkvg, p_qkvg + 768, p_qkvg + 1536, p_qkvg + 2304);
    sgemm64_kernel<<<dim3(12,16,2), 64>>>(p_o, CD, wo, wo, wo, wo, CD,
                                          nullptr, p_attout, CD, 384, NT*CD);
    cudaStreamWaitEvent(0, eTs2, 0);
    bout_kernel<<<NT*CD/256, 256>>>(bso);
    cudaStreamWaitEvent(0, eT3, 0);       // join s1 back before final
    final_kernel<<<NT*CD/256, 256>>>(bs2, (float*)d_out);
}

// round 16
// speedup vs baseline: 1.0761x; 1.0438x over previous
#include <cuda_runtime.h>
#include <cstdint>
#include <math.h>

#define NT 1024
#define CD 768
#define NH 16
#define DH 48
#define HD 1536
#define CPD 128

typedef unsigned long long ull;

// ---------------- f32x2 packed-math helpers (sm_100+) -----------------------
__device__ __forceinline__ ull pk2(float lo, float hi) {
    ull r; asm("mov.b64 %0, {%1, %2};" : "=l"(r) : "f"(lo), "f"(hi)); return r;
}
__device__ __forceinline__ void fma2(ull &d, ull a, ull b) {
    asm("fma.rn.f32x2 %0, %1, %2, %0;" : "+l"(d) : "l"(a), "l"(b));
}
__device__ __forceinline__ ull add2(ull a, ull b) {
    ull r; asm("add.rn.f32x2 %0, %1, %2;" : "=l"(r) : "l"(a), "l"(b)); return r;
}
__device__ __forceinline__ ull mul2(ull a, ull b) {
    ull r; asm("mul.rn.f32x2 %0, %1, %2;" : "=l"(r) : "l"(a), "l"(b)); return r;
}
__device__ __forceinline__ float2 up2(ull v) {
    float2 r; asm("mov.b64 {%0, %1}, %2;" : "=f"(r.x), "=f"(r.y) : "l"(v)); return r;
}
__device__ __forceinline__ float sigm(float x) { return 1.f/(1.f+__expf(-x)); }

// ---------------- scratch (device globals; no allocations allowed) ----------
__device__ __align__(16) float g_lna[NT*CD];
__device__ __align__(16) float g_sn1[NT*CD];
__device__ __align__(16) float g_sn2[NT*CD];
__device__ __align__(16) float g_an[NT*CD];
__device__ __align__(16) float g_an2[NT*CD];
__device__ __align__(16) float g_o[NT*CD];
__device__ __align__(16) float g_attout[2*NT*CD];    // split-K partials
__device__ __align__(16) float g_bout[NT*CD];
__device__ __align__(16) float g_h1[NT*HD];
__device__ __align__(16) float g_t3[2*NT*CD];        // split-K partials
__device__ __align__(16) float g_tgk[NT*2*CD];       // attn adaLN tg|tk, stride 1536
__device__ __align__(16) float g_tgk2[NT*2*CD];      // transition adaLN tg|tk
__device__ __align__(16) float g_qkvg[NT*4*CD];      // q|k|v|gate, stride 3072
__device__ __align__(16) float g_ts2[NT*2*CD];       // s@wso | s@ws2, stride 1536
__device__ __align__(16) float g_h12[NT*2*HD];       // h1|h2, stride 3072
__device__ __align__(16) float g_bqkv[4*CD];
__device__ __align__(16) float g_wgp[CPD*NH];
__device__ __align__(16) ull   g_wpk[8*CPD];         // packed h-pairs
__device__ __align__(16) float g_cc[2*NH];
__device__ __align__(16) float g_bias[(size_t)NH*NT*NT];   // 64 MB [h][q][k]

// ---------------- LayerNorm of a and s; sn1 = LN(s)*sg1, sn2 = LN(s)*sg2 ----
__global__ void ln_kernel(const float* __restrict__ a, const float* __restrict__ s,
                          const float* __restrict__ sg1, const float* __restrict__ sg2)
{
    int r = blockIdx.x, t = threadIdx.x;
    const float* ar = a + (size_t)r*CD;
    const float* sr = s + (size_t)r*CD;
    float va[3], vs[3];
    float s0=0.f,s1=0.f,s2=0.f,s3=0.f;
#pragma unroll
    for (int i=0;i<3;i++){
        va[i]=ar[t+256*i]; vs[i]=sr[t+256*i];
        s0+=va[i]; s1+=va[i]*va[i]; s2+=vs[i]; s3+=vs[i]*vs[i];
    }
    __shared__ float red[4][8];
    int lane=t&31, w=t>>5;
#pragma unroll
    for (int o=16;o;o>>=1){
        s0+=__shfl_xor_sync(0xffffffffu,s0,o);
        s1+=__shfl_xor_sync(0xffffffffu,s1,o);
        s2+=__shfl_xor_sync(0xffffffffu,s2,o);
        s3+=__shfl_xor_sync(0xffffffffu,s3,o);
    }
    if (lane==0){ red[0][w]=s0; red[1][w]=s1; red[2][w]=s2; red[3][w]=s3; }
    __syncthreads();
    float S0=0.f,S1=0.f,S2=0.f,S3=0.f;
#pragma unroll
    for (int i=0;i<8;i++){ S0+=red[0][i]; S1+=red[1][i]; S2+=red[2][i]; S3+=red[3][i]; }
    float mua=S0*(1.f/768.f), rsa=rsqrtf(S1*(1.f/768.f)-mua*mua+1e-5f);
    float mus=S2*(1.f/768.f), rss=rsqrtf(S3*(1.f/768.f)-mus*mus+1e-5f);
#pragma unroll
    for (int i=0;i<3;i++){
        int c=t+256*i; size_t idx=(size_t)r*CD+c;
        g_lna[idx]=(va[i]-mua)*rsa;
        float sv=(vs[i]-mus)*rss;
        g_sn1[idx]=sv*sg1[c];
        g_sn2[idx]=sv*sg2[c];
    }
}

__global__ void bfill_kernel(const float* __restrict__ bq)
{
    int i = blockIdx.x*256 + threadIdx.x;
    g_bqkv[i] = (i < CD) ? bq[i] : 0.f;
}

// ---------------- SGEMM: 64x128 tile, 128 threads, 8x8/thread, f32x2 --------
// Retiled from 64x64/64thr: A panel read once per 128-wide N tile (half the
// A DRAM traffic), 4 warps/CTA, half the barriers per FLOP.
__global__ void __launch_bounds__(128) sgemm128_kernel(
    const float* __restrict__ A, int lda,
    const float* __restrict__ B0, const float* __restrict__ B1,
    const float* __restrict__ B2, const float* __restrict__ B3,
    int bN, const float* __restrict__ biasv,
    float* __restrict__ C, int Nn, int K, int cz)
{
    __shared__ __align__(16) float As[2][8][64];
    __shared__ __align__(16) float Bs[2][8][128];
    int t = threadIdx.x;
    int z = blockIdx.z;
    int tx = t & 15, ty = t >> 4;            // 16 x 8 thread grid
    int row0 = blockIdx.y << 6;
    int cb = blockIdx.x;
    int perSrc = bN >> 7;
    int si = cb / perSrc;
    const float* Bsel = (si==0) ? B0 : (si==1) ? B1 : (si==2) ? B2 : B3;
    int colSrc = (cb - si*perSrc) << 7;

    // A: thread t loads row (t>>1), 4 floats at k-offset ((t&1)<<2)
    const float* Ag = A + (size_t)(row0 + (t>>1))*lda + ((t&1)<<2) + (size_t)z*K;
    // B: thread t loads k-row (t>>4), cols colSrc + (t&15)*8 (two float4)
    const float* Bg = Bsel + (size_t)z*K*bN + (size_t)(t>>4)*bN + colSrc + ((t&15)<<3);
    C += (size_t)z*cz;

    ull acc[8][4];
#pragma unroll
    for (int i=0;i<8;i++)
#pragma unroll
        for (int j=0;j<4;j++) acc[i][j]=0ull;

    int nt = K >> 3;
    float4 a0 = *(const float4*)(Ag);
    float4 b0 = *(const float4*)(Bg);
    float4 b1 = *(const float4*)(Bg + 4);
    {
        int ar = t>>1, ac = (t&1)<<2;
        As[0][ac+0][ar]=a0.x; As[0][ac+1][ar]=a0.y;
        As[0][ac+2][ar]=a0.z; As[0][ac+3][ar]=a0.w;
        *(float4*)&Bs[0][t>>4][(t&15)<<3]       = b0;
        *(float4*)&Bs[0][t>>4][((t&15)<<3) + 4] = b1;
    }
    __syncthreads();

    for (int kt = 0; kt < nt; kt++) {
        int cur = kt & 1;
        bool more = (kt+1) < nt;
        if (more) {
            a0 = *(const float4*)(Ag + (kt+1)*8);
            b0 = *(const float4*)(Bg + (size_t)(kt+1)*8*bN);
            b1 = *(const float4*)(Bg + (size_t)(kt+1)*8*bN + 4);
        }
#pragma unroll
        for (int kk = 0; kk < 8; kk++) {
            float4 av0 = *(const float4*)&As[cur][kk][ty<<3];
            float4 av1 = *(const float4*)&As[cur][kk][(ty<<3)+4];
            float4 bv0 = *(const float4*)&Bs[cur][kk][tx<<3];
            float4 bv1 = *(const float4*)&Bs[cur][kk][(tx<<3)+4];
            ull bp0 = pk2(bv0.x,bv0.y), bp1 = pk2(bv0.z,bv0.w);
            ull bp2 = pk2(bv1.x,bv1.y), bp3 = pk2(bv1.z,bv1.w);
            float aarr[8] = {av0.x,av0.y,av0.z,av0.w,av1.x,av1.y,av1.z,av1.w};
#pragma unroll
            for (int i=0;i<8;i++){
                ull aa = pk2(aarr[i], aarr[i]);
                fma2(acc[i][0], aa, bp0);
                fma2(acc[i][1], aa, bp1);
                fma2(acc[i][2], aa, bp2);
                fma2(acc[i][3], aa, bp3);
            }
        }
        if (more) {
            int nx = cur ^ 1;
            int ar = t>>1, ac = (t&1)<<2;
            As[nx][ac+0][ar]=a0.x; As[nx][ac+1][ar]=a0.y;
            As[nx][ac+2][ar]=a0.z; As[nx][ac+3][ar]=a0.w;
            *(float4*)&Bs[nx][t>>4][(t&15)<<3]       = b0;
            *(float4*)&Bs[nx][t>>4][((t&15)<<3) + 4] = b1;
            __syncthreads();
        }
    }

    int col = (cb<<7) + (tx<<3);
    float4 bb0 = make_float4(0.f,0.f,0.f,0.f), bb1 = bb0;
    if (biasv) { bb0 = *(const float4*)(biasv + col); bb1 = *(const float4*)(biasv + col + 4); }
#pragma unroll
    for (int i=0;i<8;i++){
        int r = row0 + (ty<<3) + i;
        float2 p0=up2(acc[i][0]), p1=up2(acc[i][1]), p2=up2(acc[i][2]), p3=up2(acc[i][3]);
        float4 o0 = make_float4(p0.x+bb0.x, p0.y+bb0.y, p1.x+bb0.z, p1.y+bb0.w);
        float4 o1 = make_float4(p2.x+bb1.x, p2.y+bb1.y, p3.x+bb1.z, p3.y+bb1.w);
        *(float4*)(C + (size_t)r*Nn + col) = o0;
        *(float4*)(C + (size_t)r*Nn + col + 4) = o1;
    }
}

// ---------------- adaLN combine: an = sigmoid(tg+bg)*lna + tk ---------------
__global__ void adaln_combine_kernel(const float* __restrict__ tgk,
                                     const float* __restrict__ bgv,
                                     float* __restrict__ outp)
{
    int i = blockIdx.x*256 + threadIdx.x;
    int r = i / CD, c = i - r*CD;
    float tg = tgk[(size_t)r*1536 + c];
    float tk = tgk[(size_t)r*1536 + 768 + c];
    outp[i] = sigm(tg + bgv[c])*g_lna[i] + tk;
}

// ---------------- pair-bias precompute: wgp, packed h-pairs, c1/c2 ----------
__global__ void pair_prep_kernel(const float* __restrict__ gp,
                                 const float* __restrict__ bp,
                                 const float* __restrict__ wp)
{
    int j = threadIdx.x;  // 128
    float wg[NH];
#pragma unroll
    for (int h=0; h<NH; h++){ wg[h] = gp[j]*wp[j*NH+h]; g_wgp[j*NH+h] = wg[h]; }
#pragma unroll
    for (int m=0; m<8; m++) g_wpk[m*CPD + j] = pk2(wg[2*m], wg[2*m+1]);
    __syncthreads();
    if (j < NH) {
        float c1=0.f, c2=0.f;
        for (int jj=0; jj<CPD; jj++){ c1 += bp[jj]*wp[jj*NH+j]; c2 += g_wgp[jj*NH+j]; }
        g_cc[j]=c1; g_cc[NH+j]=c2;
    }
}

// ---------------- pair bias v6: 256 pairs/block, 1 pair/thread, LDS.128 -----
#define PB_SMEM (256*36*4 + 128*8*8)
__global__ void __launch_bounds__(256) pair_bias_kernel(
    const float* __restrict__ pair, const float* __restrict__ beta)
{
    extern __shared__ __align__(16) float smem[];
    float* xs = smem;                         // [256][36]
    ull* wks = (ull*)(smem + 256*36);         // [128 k][8 m]
    __shared__ float csm[2*NH];

    int t = threadIdx.x;
    int q = blockIdx.x >> 2;
    int k0 = (blockIdx.x & 3) << 8;           // 0,256,512,768

    for (int i = t; i < 1024; i += 256) {
        int k = i >> 3, m = i & 7;
        wks[(k<<3) + m] = g_wpk[m*CPD + k];
    }
    if (t < 2*NH) csm[t] = g_cc[t];

    ull acc[8];
#pragma unroll
    for (int m=0;m<8;m++) acc[m]=0ull;
    float sm = 0.f, sq = 0.f;

    const float* base = pair + (((size_t)q<<10) + k0)*CPD;

    for (int c = 0; c < 4; c++) {
        __syncthreads();
#pragma unroll
        for (int it=0; it<8; it++) {
            int g = (it<<8) + t;
            int row = g >> 3, j = g & 7;
            *(float4*)(xs + row*36 + (j<<2)) =
                *(const float4*)(base + (size_t)row*CPD + (c<<5) + (j<<2));
        }
        __syncthreads();
        const float* xrow = xs + t*36;
#pragma unroll
        for (int kk=0; kk<32; kk++) {
            const ulonglong2* wr = (const ulonglong2*)(wks + ((c<<5)+kk)*8);
            ulonglong2 w01 = wr[0];
            ulonglong2 w23 = wr[1];
            ulonglong2 w45 = wr[2];
            ulonglong2 w67 = wr[3];
            float xv = xrow[kk];
            sm += xv;
            sq = fmaf(xv, xv, sq);
            ull xx = pk2(xv, xv);
            fma2(acc[0], xx, w01.x); fma2(acc[1], xx, w01.y);
            fma2(acc[2], xx, w23.x); fma2(acc[3], xx, w23.y);
            fma2(acc[4], xx, w45.x); fma2(acc[5], xx, w45.y);
            fma2(acc[6], xx, w67.x); fma2(acc[7], xx, w67.y);
        }
    }

    {
        int kk = k0 + t;
        float mu = sm*(1.f/128.f);
        float rs = rsqrtf(sq*(1.f/128.f) - mu*mu + 1e-5f);
        float murs = mu*rs;
        float bv = beta[((size_t)q<<10) + kk];
#pragma unroll
        for (int m=0;m<8;m++){
            float2 v = up2(acc[m]);
            int h0 = m<<1;
            float z0 = rs*v.x - murs*csm[NH+h0]   + csm[h0]   + bv;
            float z1 = rs*v.y - murs*csm[NH+h0+1] + csm[h0+1] + bv;
            g_bias[((size_t)h0<<20)     + ((size_t)q<<10) + kk] = z0;
            g_bias[((size_t)(h0+1)<<20) + ((size_t)q<<10) + kk] = z1;
        }
    }
}

// ---------------- flash attention (f32x2) + fused output gate (R9) ----------
__global__ void __launch_bounds__(128) attn_kernel(
    const float* __restrict__ qp, const float* __restrict__ kp,
    const float* __restrict__ vp, const float* __restrict__ gatep)
{
    __shared__ __align__(16) float pool[6144];
    __shared__ float Ms[64], Ls[64];
    int t = threadIdx.x;
    int half = t>>6, ql = t&63;
    int h = blockIdx.y;
    int qr = (blockIdx.x<<6) + ql;
    const float scale = 0.14433756729740643f;
    ull q2[24];
#pragma unroll
    for (int d4=0; d4<12; d4++){
        float4 qq = *(const float4*)(qp + (size_t)qr*3072 + h*48 + (d4<<2));
        q2[d4*2]   = pk2(qq.x*scale, qq.y*scale);
        q2[d4*2+1] = pk2(qq.z*scale, qq.w*scale);
    }
    float m = -1e30f, l = 0.f;
    ull acc2[24];
#pragma unroll
    for (int i=0;i<24;i++) acc2[i]=0ull;
    int kb = half<<9;
    const float* brow = g_bias + ((size_t)h<<20) + ((size_t)qr<<10) + kb;
    for (int kt=0; kt<512; kt+=32) {
        __syncthreads();
#pragma unroll
        for (int it=0; it<6; it++) {
            int i4 = t + (it<<7);
            int d4 = i4 % 12;
            int rem = i4 / 12;
            int j = rem & 31, hh = rem >> 5;
            int krow = (hh<<9) + kt + j;
            ((float4*)pool)[i4]      = *(const float4*)(kp + (size_t)krow*3072 + h*48 + (d4<<2));
            ((float4*)pool)[768+i4]  = *(const float4*)(vp + (size_t)krow*3072 + h*48 + (d4<<2));
        }
        __syncthreads();
        float bb[32];
#pragma unroll
        for (int i=0;i<8;i++){
            float4 b4 = *(const float4*)(brow + kt + (i<<2));
            bb[i*4]=b4.x; bb[i*4+1]=b4.y; bb[i*4+2]=b4.z; bb[i*4+3]=b4.w;
        }
        const float* Kt = pool + half*1536;
        const float* Vt = pool + 3072 + half*1536;
        for (int j=0; j<32; j++) {
            const ull* kr2 = (const ull*)(Kt + j*48);
            ull d2 = 0ull;
#pragma unroll
            for (int i=0;i<24;i++) fma2(d2, q2[i], kr2[i]);
            float2 dd = up2(d2);
            float sc = dd.x + dd.y + bb[j];
            if (sc > m) {
                float corr = __expf(m - sc);
                l *= corr;
                ull cp = pk2(corr, corr);
#pragma unroll
                for (int i=0;i<24;i++) acc2[i] = mul2(acc2[i], cp);
                m = sc;
            }
            float pw = __expf(sc - m);
            l += pw;
            ull pp = pk2(pw, pw);
            const ull* vr2 = (const ull*)(Vt + j*48);
#pragma unroll
            for (int i=0;i<24;i++) fma2(acc2[i], pp, vr2[i]);
        }
    }
    __syncthreads();
    if (half == 1) {
        Ms[ql]=m; Ls[ql]=l;
#pragma unroll
        for (int i=0;i<24;i++){
            float2 v = up2(acc2[i]);
            pool[ql*48+2*i]=v.x; pool[ql*48+2*i+1]=v.y;
        }
    }
    __syncthreads();
    if (half == 0) {
        float m2=Ms[ql], l2=Ls[ql];
        float mn=fmaxf(m,m2);
        float c1=__expf(m-mn), c2=__expf(m2-mn);
        float inv=1.f/(l*c1 + l2*c2);
#pragma unroll
        for (int i=0;i<24;i++){
            float2 v = up2(acc2[i]);
            float g0 = sigm(gatep[(size_t)qr*3072 + h*48 + 2*i]);
            float g1 = sigm(gatep[(size_t)qr*3072 + h*48 + 2*i+1]);
            g_o[(size_t)qr*CD + h*48 + 2*i]   = (v.x*c1 + pool[ql*48+2*i]*c2)*inv*g0;
            g_o[(size_t)qr*CD + h*48 + 2*i+1] = (v.y*c1 + pool[ql*48+2*i+1]*c2)*inv*g1;
        }
    }
}

// ---------------- small elementwise kernels ---------------------------------
__global__ void bout_kernel(const float* __restrict__ bso) {
    int i = blockIdx.x*256 + threadIdx.x;
    int r = i / CD, c = i - r*CD;
    float att = g_attout[i] + g_attout[NT*CD + i];
    g_bout[i] = sigm(g_ts2[(size_t)r*1536 + c] + bso[c])*att;
}
__global__ void swiglu_kernel() {
    int i = blockIdx.x*256 + threadIdx.x;
    int r = i / HD, c = i - r*HD;
    float x = g_h12[(size_t)r*3072 + c];
    float y = g_h12[(size_t)r*3072 + 1536 + c];
    g_h1[i] = x*sigm(x)*y;
}
__global__ void final_kernel(const float* __restrict__ bs2, float* __restrict__ outp) {
    int i = blockIdx.x*256 + threadIdx.x;
    int r = i / CD, c = i - r*CD;
    float t3 = g_t3[i] + g_t3[NT*CD + i];
    outp[i] = g_bout[i] + sigm(g_ts2[(size_t)r*1536 + 768 + c] + bs2[c])*t3;
}

// ---------------- launch: dual-stream overlap (R15 schedule) -----------------
extern "C" void kernel_launch(void* const* d_in, const int* in_sizes, int n_in,
                              void* d_out, int out_size)
{
    (void)in_sizes; (void)n_in; (void)out_size;
    const float* a     = (const float*)d_in[0];
    const float* s     = (const float*)d_in[1];
    const float* pair  = (const float*)d_in[2];
    const float* beta  = (const float*)d_in[3];
    const float* sg1   = (const float*)d_in[4];
    const float* wg1   = (const float*)d_in[5];
    const float* bg1   = (const float*)d_in[6];
    const float* wsk1  = (const float*)d_in[7];
    const float* wq    = (const float*)d_in[8];
    const float* bq    = (const float*)d_in[9];
    const float* wk    = (const float*)d_in[10];
    const float* wv    = (const float*)d_in[11];
    const float* gp    = (const float*)d_in[12];
    const float* bp    = (const float*)d_in[13];
    const float* wp    = (const float*)d_in[14];
    const float* wgate = (const float*)d_in[15];
    const float* wo    = (const float*)d_in[16];
    const float* wso   = (const float*)d_in[17];
    const float* bso   = (const float*)d_in[18];
    const float* sg2   = (const float*)d_in[19];
    const float* wg2   = (const float*)d_in[20];
    const float* bg2   = (const float*)d_in[21];
    const float* wsk2  = (const float*)d_in[22];
    const float* w1    = (const float*)d_in[23];
    const float* w2    = (const float*)d_in[24];
    const float* w3    = (const float*)d_in[25];
    const float* ws2   = (const float*)d_in[26];
    const float* bs2   = (const float*)d_in[27];

    float *p_sn1,*p_sn2,*p_an,*p_an2,*p_o,*p_attout,*p_h1,*p_t3,*p_tgk,*p_tgk2,
          *p_qkvg,*p_ts2,*p_h12,*p_bqkv;
    cudaGetSymbolAddress((void**)&p_sn1,   g_sn1);
    cudaGetSymbolAddress((void**)&p_sn2,   g_sn2);
    cudaGetSymbolAddress((void**)&p_an,    g_an);
    cudaGetSymbolAddress((void**)&p_an2,   g_an2);
    cudaGetSymbolAddress((void**)&p_o,     g_o);
    cudaGetSymbolAddress((void**)&p_attout,g_attout);
    cudaGetSymbolAddress((void**)&p_h1,    g_h1);
    cudaGetSymbolAddress((void**)&p_t3,    g_t3);
    cudaGetSymbolAddress((void**)&p_tgk,   g_tgk);
    cudaGetSymbolAddress((void**)&p_tgk2,  g_tgk2);
    cudaGetSymbolAddress((void**)&p_qkvg,  g_qkvg);
    cudaGetSymbolAddress((void**)&p_ts2,   g_ts2);
    cudaGetSymbolAddress((void**)&p_h12,   g_h12);
    cudaGetSymbolAddress((void**)&p_bqkv,  g_bqkv);

    static cudaStream_t s1 = nullptr;
    static cudaEvent_t eFork, ePair, eTs2, eT3;
    if (!s1) {
        cudaFuncSetAttribute(pair_bias_kernel,
                             cudaFuncAttributeMaxDynamicSharedMemorySize, PB_SMEM);
        cudaStreamCreateWithFlags(&s1, cudaStreamNonBlocking);
        cudaEventCreateWithFlags(&eFork, cudaEventDisableTiming);
        cudaEventCreateWithFlags(&ePair, cudaEventDisableTiming);
        cudaEventCreateWithFlags(&eTs2,  cudaEventDisableTiming);
        cudaEventCreateWithFlags(&eT3,   cudaEventDisableTiming);
    }

    // ---- prep (legacy stream) ----
    ln_kernel<<<NT, 256>>>(a, s, sg1, sg2);
    pair_prep_kernel<<<1, 128>>>(gp, bp, wp);
    bfill_kernel<<<12, 256>>>(bq);

    // ---- fork: s1 carries pair_bias + ts2 + transition chain ----
    cudaEventRecord(eFork, 0);
    cudaStreamWaitEvent(s1, eFork, 0);

    pair_bias_kernel<<<4096, 256, PB_SMEM, s1>>>(pair, beta);
    cudaEventRecord(ePair, s1);
    sgemm128_kernel<<<dim3(12,16,1), 128, 0, s1>>>(s, CD, wso, ws2, wso, wso, CD,
                                                   nullptr, p_ts2, 1536, CD, 0);
    cudaEventRecord(eTs2, s1);
    sgemm128_kernel<<<dim3(12,16,1), 128, 0, s1>>>(p_sn2, CD, wg2, wsk2, wg2, wg2, CD,
                                                   nullptr, p_tgk2, 1536, CD, 0);
    adaln_combine_kernel<<<NT*CD/256, 256, 0, s1>>>(p_tgk2, bg2, p_an2);
    sgemm128_kernel<<<dim3(24,16,1), 128, 0, s1>>>(p_an2, CD, w1, w2, w1, w1, HD,
                                                   nullptr, p_h12, 3072, CD, 0);
    swiglu_kernel<<<NT*HD/256, 256, 0, s1>>>();
    sgemm128_kernel<<<dim3(6,16,2), 128, 0, s1>>>(p_h1, HD, w3, w3, w3, w3, CD,
                                                  nullptr, p_t3, CD, CD, NT*CD);
    cudaEventRecord(eT3, s1);

    // ---- legacy stream: attention chain ----
    sgemm128_kernel<<<dim3(12,16,1), 128>>>(p_sn1, CD, wg1, wsk1, wg1, wg1, CD,
                                            nullptr, p_tgk, 1536, CD, 0);
    adaln_combine_kernel<<<NT*CD/256, 256>>>(p_tgk, bg1, p_an);
    sgemm128_kernel<<<dim3(24,16,1), 128>>>(p_an, CD, wq, wk, wv, wgate, CD,
                                            p_bqkv, p_qkvg, 3072, CD, 0);
    cudaStreamWaitEvent(0, ePair, 0);
    attn_kernel<<<dim3(16, 16), 128>>>(p_qkvg, p_qkvg + 768, p_qkvg + 1536, p_qkvg + 2304);
    sgemm128_kernel<<<dim3(6,16,2), 128>>>(p_o, CD, wo, wo, wo, wo, CD,
                                           nullptr, p_attout, CD, 384, NT*CD);
    cudaStreamWaitEvent(0, eTs2, 0);
    bout_kernel<<<NT*CD/256, 256>>>(bso);
    cudaStreamWaitEvent(0, eT3, 0);       // join s1 back before final
    final_kernel<<<NT*CD/256, 256>>>(bs2, (float*)d_out);
}